// round 13
// baseline (speedup 1.0000x reference)
#include <cuda_runtime.h>
#include <cuda_fp16.h>
#include <math.h>

#define V_   50257
#define VP2_ 50304            // V padded to multiple of 128 (half scratch row stride)
#define NBLK_ 393             // vocab n-tiles of 128
#define D_   768
#define S_   2048
#define B_   2
#define HID_ 2048
#define NH_  12
#define HD_  64
#define T_   (B_*S_)   // 4096 tokens
#define NEG_ -1e30f

// ---------------- scratch (device globals; no allocation allowed) ----------
__device__ __half g_x  [T_*D_];
__device__ __half g_q  [T_*D_];
__device__ __half g_k  [T_*D_];
__device__ __half g_v  [T_*D_];
__device__ __half g_ctx[T_*D_];
__device__ __half g_ao [T_*D_];
__device__ __half g_h1 [T_*HID_];
__device__ float  g_h2 [T_*D_];
__device__ __half g_hn [T_*D_];
__device__ float  g_rowloss[T_];
__device__ float  g_pmax[T_*NBLK_];
__device__ float  g_psum[T_*NBLK_];
__device__ float  g_bqkv[3*D_];
// fp16 weight scratch: wqkv | wo | w1 | w2 | w_out(padded)  — CONTIGUOUS regions
#define OFF_WQKV 0
#define OFF_WO   (OFF_WQKV + D_*3*D_)
#define OFF_W1   (OFF_WO + D_*D_)
#define OFF_W2   (OFF_W1 + D_*HID_)
#define OFF_WOUT (OFF_W2 + HID_*D_)
#define W_TOTAL  (OFF_WOUT + D_*VP2_ + 64)
__device__ __half g_w[W_TOTAL];

// ---------------- fused weight conversion (ONE launch) -----------------------
#define CN0 221184L
#define CN1 (CN0 + 73728L)
#define CN2 (CN1 + 196608L)
#define CN3 (CN2 + 196608L)
#define CN4 (CN3 + 4829184L)
#define CN5 (CN4 + 288L)

__device__ __forceinline__ void cvt8(const float* __restrict__ src, __half* dst) {
    float4 a = *(const float4*)src;
    float4 b = *(const float4*)(src + 4);
    __half h[8] = { __float2half(a.x), __float2half(a.y), __float2half(a.z), __float2half(a.w),
                    __float2half(b.x), __float2half(b.y), __float2half(b.z), __float2half(b.w) };
    *(uint4*)dst = *(const uint4*)h;
}

__global__ void convert_all_kernel(const float* __restrict__ wq, const float* __restrict__ wk,
                                   const float* __restrict__ wv, const float* __restrict__ wo,
                                   const float* __restrict__ w1, const float* __restrict__ w2,
                                   const float* __restrict__ wout,
                                   const float* __restrict__ bq, const float* __restrict__ bk,
                                   const float* __restrict__ bv,
                                   __half* __restrict__ w, float* __restrict__ bqkv)
{
    long j = (long)blockIdx.x * blockDim.x + threadIdx.x;
    if (j >= CN5) return;
    if (j < CN0) {
        long off = j * 8;
        int r = (int)(off / (3*D_)), rem = (int)(off % (3*D_));
        int sel = rem / D_, c = rem % D_;
        const float* src = (sel == 0 ? wq : sel == 1 ? wk : wv) + (size_t)r * D_ + c;
        cvt8(src, w + off);
    } else if (j < CN1) {
        cvt8(wo + (j - CN0) * 8, w + j * 8);
    } else if (j < CN2) {
        cvt8(w1 + (j - CN1) * 8, w + j * 8);
    } else if (j < CN3) {
        cvt8(w2 + (j - CN2) * 8, w + j * 8);
    } else if (j < CN4) {
        long jj = j - CN3;
        int r = (int)(jj / (VP2_/8));
        int c = (int)(jj % (VP2_/8)) * 8;
        const float* src = wout + (size_t)r * V_ + c;
        __half tmp[8];
#pragma unroll
        for (int e = 0; e < 8; e++)
            tmp[e] = (c + e < V_) ? __float2half(__ldg(src + e)) : __half(0.f);
        *(uint4*)(w + j * 8) = *(const uint4*)tmp;
    } else {
        int i = (int)(j - CN4) * 8;
#pragma unroll
        for (int e = 0; e < 8; e++) {
            int idx = i + e;
            int sel = idx / D_, c = idx - sel * D_;
            bqkv[idx] = (sel == 0 ? bq : sel == 1 ? bk : bv)[c];
        }
    }
}

// ---------------- embedding + sinusoidal positional encoding ---------------
__global__ void embed_kernel(const int* __restrict__ inputs,
                             const float* __restrict__ wte,
                             __half* __restrict__ x)
{
    int idx = blockIdx.x * blockDim.x + threadIdx.x;
    if (idx >= T_*D_) return;
    int t = idx / D_;
    int d = idx - t * D_;
    int s = t & (S_-1);
    int tok = inputs[t];
    int i2 = (d >> 1) * 2;
    float div = expf((float)(-i2) * (logf(10000.0f) / (float)D_));
    float ang = (float)s * div;
    float pe = (d & 1) ? cosf(ang) : sinf(ang);
    x[idx] = __float2half(wte[(size_t)tok * D_ + d] + pe);
}

// ---------------- fp16 tensor-core GEMM (BM=128), 3-stage cp.async -----------
// modes: 0 = f32 out, 1 = f16 out, 2 = qkv split f16 out
#define AST2 40
#define BST2 136
#define ASTB (128*AST2*2)
#define STGB (ASTB + 32*BST2*2)

__global__ __launch_bounds__(256, 2)
void hgemm_kernel(const __half* __restrict__ A, const __half* __restrict__ W,
                  const float* __restrict__ bias, void* __restrict__ Cout,
                  __half* __restrict__ dq, __half* __restrict__ dk, __half* __restrict__ dv,
                  int M, int N, int K, int ldW, int relu, int mode)
{
    extern __shared__ char smc[];
    const int tid  = threadIdx.x;
    const int warp = tid >> 5;
    const int lane = tid & 31;
    const int gid  = lane >> 2;
    const int tig  = lane & 3;
    const int wm   = warp >> 2;
    const int wn   = warp & 3;
    const int m0 = blockIdx.x * 128;
    const int n0 = blockIdx.y * 128;
    const unsigned smem0 = (unsigned)__cvta_generic_to_shared(smc);

    float acc[4][4][4];
#pragma unroll
    for (int i = 0; i < 4; i++)
#pragma unroll
        for (int j = 0; j < 4; j++)
#pragma unroll
            for (int c = 0; c < 4; c++) acc[i][j][c] = 0.f;

    const int nk = K >> 5;

    auto load_stage = [&](int i) {
        unsigned sa = smem0 + (i % 3) * STGB;
        unsigned sb = sa + ASTB;
        const __half* Ab = A + (size_t)m0 * K + i * 32;
        const __half* Bb = W + (size_t)(i * 32) * ldW + n0;
#pragma unroll
        for (int t = 0; t < 2; t++) {
            int slot = t * 256 + tid;
            int r = slot >> 2, c = (slot & 3) * 8;
            asm volatile("cp.async.cg.shared.global [%0], [%1], 16;"
                         :: "r"(sa + (r * AST2 + c) * 2), "l"(Ab + (size_t)r * K + c));
        }
#pragma unroll
        for (int t = 0; t < 2; t++) {
            int slot = t * 256 + tid;
            int r = slot >> 4, c = (slot & 15) * 8;
            asm volatile("cp.async.cg.shared.global [%0], [%1], 16;"
                         :: "r"(sb + (r * BST2 + c) * 2), "l"(Bb + (size_t)r * ldW + c));
        }
        asm volatile("cp.async.commit_group;");
    };

    load_stage(0);
    load_stage(1);
    asm volatile("cp.async.wait_group 1;");
    __syncthreads();

    const int arow = lane & 15;
    const int acol = (lane >> 4) * 8;

    for (int i = 0; i < nk; i++) {
        unsigned sa = smem0 + (i % 3) * STGB;
        unsigned sb = sa + ASTB;

        if (i + 2 < nk) load_stage(i + 2);
        else            asm volatile("cp.async.commit_group;");

#pragma unroll
        for (int kk = 0; kk < 32; kk += 16) {
            unsigned af[4][4], bf[4][2];
#pragma unroll
            for (int mi = 0; mi < 4; mi++) {
                unsigned ad = sa + ((wm * 64 + mi * 16 + arow) * AST2 + kk + acol) * 2;
                asm volatile("ldmatrix.sync.aligned.m8n8.x4.shared.b16 {%0,%1,%2,%3}, [%4];"
                             : "=r"(af[mi][0]), "=r"(af[mi][1]),
                               "=r"(af[mi][2]), "=r"(af[mi][3]) : "r"(ad));
            }
#pragma unroll
            for (int nh = 0; nh < 2; nh++) {
                unsigned bd = sb + ((kk + arow) * BST2 + wn * 32 + nh * 16 + acol) * 2;
                asm volatile("ldmatrix.sync.aligned.m8n8.x4.trans.shared.b16 {%0,%1,%2,%3}, [%4];"
                             : "=r"(bf[2*nh][0]), "=r"(bf[2*nh][1]),
                               "=r"(bf[2*nh+1][0]), "=r"(bf[2*nh+1][1]) : "r"(bd));
            }
#pragma unroll
            for (int mi = 0; mi < 4; mi++)
#pragma unroll
                for (int ni = 0; ni < 4; ni++) {
                    asm volatile(
                        "mma.sync.aligned.m16n8k16.row.col.f32.f16.f16.f32 "
                        "{%0,%1,%2,%3},{%4,%5,%6,%7},{%8,%9},{%0,%1,%2,%3};"
                        : "+f"(acc[mi][ni][0]), "+f"(acc[mi][ni][1]),
                          "+f"(acc[mi][ni][2]), "+f"(acc[mi][ni][3])
                        : "r"(af[mi][0]), "r"(af[mi][1]),
                          "r"(af[mi][2]), "r"(af[mi][3]),
                          "r"(bf[ni][0]), "r"(bf[ni][1]));
                }
        }

        asm volatile("cp.async.wait_group 1;");
        __syncthreads();
    }

    __half* qdst = 0; int qcol0 = 0;
    if (mode == 2) {
        int sel = n0 / D_;
        qdst  = (sel == 0 ? dq : sel == 1 ? dk : dv);
        qcol0 = n0 - sel * D_;
    }

#pragma unroll
    for (int mi = 0; mi < 4; mi++) {
        int r = m0 + wm * 64 + mi * 16 + gid;
#pragma unroll
        for (int ni = 0; ni < 4; ni++) {
            int cc = n0 + wn * 32 + ni * 8 + tig * 2;
            float b0 = bias[cc], b1 = bias[cc + 1];
            float v0 = acc[mi][ni][0] + b0;
            float v1 = acc[mi][ni][1] + b1;
            float v2 = acc[mi][ni][2] + b0;
            float v3 = acc[mi][ni][3] + b1;
            if (relu) {
                v0 = fmaxf(v0, 0.f); v1 = fmaxf(v1, 0.f);
                v2 = fmaxf(v2, 0.f); v3 = fmaxf(v3, 0.f);
            }
            if (mode == 1) {
                __half2 h0 = __floats2half2_rn(v0, v1);
                __half2 h1 = __floats2half2_rn(v2, v3);
                *(__half2*)((__half*)Cout + (size_t)r * N + cc)       = h0;
                *(__half2*)((__half*)Cout + (size_t)(r + 8) * N + cc) = h1;
            } else if (mode == 2) {
                int lc = qcol0 + (cc - n0);
                __half2 h0 = __floats2half2_rn(v0, v1);
                __half2 h1 = __floats2half2_rn(v2, v3);
                *(__half2*)(qdst + (size_t)r * D_ + lc)       = h0;
                *(__half2*)(qdst + (size_t)(r + 8) * D_ + lc) = h1;
            } else {
                float* C = (float*)Cout;
                C[(size_t)r * N + cc]           = v0;
                C[(size_t)r * N + cc + 1]       = v1;
                C[(size_t)(r + 8) * N + cc]     = v2;
                C[(size_t)(r + 8) * N + cc + 1] = v3;
            }
        }
    }
}

// ---------------- fp16 GEMM BM=256 x BN=128 (vocab + loss partials) ----------
// 8 warps as 4x2, warp tile 64x64: 32 MMA : 8 LDSM per k-step. 1 CTA/SM.
#define A6STB (256*AST2*2)                 // 20480 B
#define STG6B (A6STB + 32*BST2*2)          // 29184 B per stage

__global__ __launch_bounds__(256, 1)
void hgemm256_kernel(const __half* __restrict__ A, const __half* __restrict__ W,
                     const float* __restrict__ bias, float* __restrict__ C,
                     float* __restrict__ pmax, float* __restrict__ psum, int nblk,
                     int M, int N, int K, int ldW)
{
    extern __shared__ char smc[];
    const int tid  = threadIdx.x;
    const int warp = tid >> 5;
    const int lane = tid & 31;
    const int gid  = lane >> 2;
    const int tig  = lane & 3;
    const int wm   = warp >> 1;      // 0..3 (64-row slices)
    const int wn   = warp & 1;       // 0..1 (64-col slices)
    const int m0 = blockIdx.x * 256;
    const int n0 = blockIdx.y * 128;
    const unsigned smem0 = (unsigned)__cvta_generic_to_shared(smc);

    float acc[4][8][4];
#pragma unroll
    for (int i = 0; i < 4; i++)
#pragma unroll
        for (int j = 0; j < 8; j++)
#pragma unroll
            for (int c = 0; c < 4; c++) acc[i][j][c] = 0.f;

    const int nk = K >> 5;

    auto load_stage = [&](int i) {
        unsigned sa = smem0 + (i % 3) * STG6B;
        unsigned sb = sa + A6STB;
        const __half* Ab = A + (size_t)m0 * K + i * 32;
        const __half* Bb = W + (size_t)(i * 32) * ldW + n0;
#pragma unroll
        for (int t = 0; t < 4; t++) {
            int slot = t * 256 + tid;
            int r = slot >> 2, c = (slot & 3) * 8;
            asm volatile("cp.async.cg.shared.global [%0], [%1], 16;"
                         :: "r"(sa + (r * AST2 + c) * 2), "l"(Ab + (size_t)r * K + c));
        }
#pragma unroll
        for (int t = 0; t < 2; t++) {
            int slot = t * 256 + tid;
            int r = slot >> 4, c = (slot & 15) * 8;
            asm volatile("cp.async.cg.shared.global [%0], [%1], 16;"
                         :: "r"(sb + (r * BST2 + c) * 2), "l"(Bb + (size_t)r * ldW + c));
        }
        asm volatile("cp.async.commit_group;");
    };

    load_stage(0);
    load_stage(1);
    asm volatile("cp.async.wait_group 1;");
    __syncthreads();

    const int arow = lane & 15;
    const int acol = (lane >> 4) * 8;

    for (int i = 0; i < nk; i++) {
        unsigned sa = smem0 + (i % 3) * STG6B;
        unsigned sb = sa + A6STB;

        if (i + 2 < nk) load_stage(i + 2);
        else            asm volatile("cp.async.commit_group;");

#pragma unroll
        for (int kk = 0; kk < 32; kk += 16) {
            unsigned af[4][4], bf[8][2];
#pragma unroll
            for (int mi = 0; mi < 4; mi++) {
                unsigned ad = sa + ((wm * 64 + mi * 16 + arow) * AST2 + kk + acol) * 2;
                asm volatile("ldmatrix.sync.aligned.m8n8.x4.shared.b16 {%0,%1,%2,%3}, [%4];"
                             : "=r"(af[mi][0]), "=r"(af[mi][1]),
                               "=r"(af[mi][2]), "=r"(af[mi][3]) : "r"(ad));
            }
#pragma unroll
            for (int nh = 0; nh < 4; nh++) {
                unsigned bd = sb + ((kk + arow) * BST2 + wn * 64 + nh * 16 + acol) * 2;
                asm volatile("ldmatrix.sync.aligned.m8n8.x4.trans.shared.b16 {%0,%1,%2,%3}, [%4];"
                             : "=r"(bf[2*nh][0]), "=r"(bf[2*nh][1]),
                               "=r"(bf[2*nh+1][0]), "=r"(bf[2*nh+1][1]) : "r"(bd));
            }
#pragma unroll
            for (int mi = 0; mi < 4; mi++)
#pragma unroll
                for (int ni = 0; ni < 8; ni++) {
                    asm volatile(
                        "mma.sync.aligned.m16n8k16.row.col.f32.f16.f16.f32 "
                        "{%0,%1,%2,%3},{%4,%5,%6,%7},{%8,%9},{%0,%1,%2,%3};"
                        : "+f"(acc[mi][ni][0]), "+f"(acc[mi][ni][1]),
                          "+f"(acc[mi][ni][2]), "+f"(acc[mi][ni][3])
                        : "r"(af[mi][0]), "r"(af[mi][1]),
                          "r"(af[mi][2]), "r"(af[mi][3]),
                          "r"(bf[ni][0]), "r"(bf[ni][1]));
                }
        }

        asm volatile("cp.async.wait_group 1;");
        __syncthreads();
    }

    float* red = (float*)smc;   // [256 rows][2 wn][2] = 4KB (pipeline done)

#pragma unroll
    for (int mi = 0; mi < 4; mi++) {
        int rl = wm * 64 + mi * 16 + gid;   // local row (half 0); +8 for half 1
        int r  = m0 + rl;
        float mA = NEG_, sA = 0.f, mB = NEG_, sB = 0.f;
#pragma unroll
        for (int ni = 0; ni < 8; ni++) {
            int cc = n0 + wn * 64 + ni * 8 + tig * 2;
            bool full = (cc + 1 < N);
            bool any  = (cc < N);
            float b0 = any  ? bias[cc]     : 0.f;
            float b1 = full ? bias[cc + 1] : 0.f;
            float v0 = acc[mi][ni][0] + b0;
            float v1 = acc[mi][ni][1] + b1;
            float v2 = acc[mi][ni][2] + b0;
            float v3 = acc[mi][ni][3] + b1;
            if (any) {
                asm volatile("st.global.cs.f32 [%0], %1;" :: "l"(C + (size_t)r * N + cc), "f"(v0));
                asm volatile("st.global.cs.f32 [%0], %1;" :: "l"(C + (size_t)(r + 8) * N + cc), "f"(v2));
                if (v0 > mA) { sA = sA * __expf(mA - v0) + 1.f; mA = v0; }
                else         { sA += __expf(v0 - mA); }
                if (v2 > mB) { sB = sB * __expf(mB - v2) + 1.f; mB = v2; }
                else         { sB += __expf(v2 - mB); }
            }
            if (full) {
                asm volatile("st.global.cs.f32 [%0], %1;" :: "l"(C + (size_t)r * N + cc + 1), "f"(v1));
                asm volatile("st.global.cs.f32 [%0], %1;" :: "l"(C + (size_t)(r + 8) * N + cc + 1), "f"(v3));
                if (v1 > mA) { sA = sA * __expf(mA - v1) + 1.f; mA = v1; }
                else         { sA += __expf(v1 - mA); }
                if (v3 > mB) { sB = sB * __expf(mB - v3) + 1.f; mB = v3; }
                else         { sB += __expf(v3 - mB); }
            }
        }
        // quad reduce over tig lanes
#pragma unroll
        for (int o = 1; o <= 2; o <<= 1) {
            float m2 = __shfl_xor_sync(0xffffffffu, mA, o);
            float s2 = __shfl_xor_sync(0xffffffffu, sA, o);
            float mm = fmaxf(mA, m2);
            sA = sA * __expf(mA - mm) + s2 * __expf(m2 - mm);
            mA = mm;
            m2 = __shfl_xor_sync(0xffffffffu, mB, o);
            s2 = __shfl_xor_sync(0xffffffffu, sB, o);
            mm = fmaxf(mB, m2);
            sB = sB * __expf(mB - mm) + s2 * __expf(m2 - mm);
            mB = mm;
        }
        if (tig == 0) {
            red[((rl    ) * 2 + wn) * 2 + 0] = mA;
            red[((rl    ) * 2 + wn) * 2 + 1] = sA;
            red[((rl + 8) * 2 + wn) * 2 + 0] = mB;
            red[((rl + 8) * 2 + wn) * 2 + 1] = sB;
        }
    }

    __syncthreads();
    {
        float m = NEG_, s = 0.f;
#pragma unroll
        for (int wnn = 0; wnn < 2; wnn++) {
            float m2 = red[(tid * 2 + wnn) * 2 + 0];
            float s2 = red[(tid * 2 + wnn) * 2 + 1];
            float mm = fmaxf(m, m2);
            s = s * __expf(m - mm) + s2 * __expf(m2 - mm);
            m = mm;
        }
        pmax[(size_t)(m0 + tid) * nblk + blockIdx.y] = m;
        psum[(size_t)(m0 + tid) * nblk + blockIdx.y] = s;
    }
}

// ---------------- tensor-core flash attention (FA2 layout) -------------------
#define ATS 72

__global__ __launch_bounds__(128)
void attn_tc_kernel(const __half* __restrict__ Q, const __half* __restrict__ K,
                    const __half* __restrict__ V, __half* __restrict__ O)
{
    __shared__ __half Qs[64*ATS];
    __shared__ __half Ks[64*ATS];
    __shared__ __half Vs[64*ATS];

    const int qt = (int)gridDim.x - 1 - (int)blockIdx.x;   // heavy tiles first
    const int bh = blockIdx.y;
    const int b  = bh / NH_;
    const int h  = bh - b * NH_;

    const int tid  = threadIdx.x;
    const int w    = tid >> 5;
    const int lane = tid & 31;
    const int gid  = lane >> 2;
    const int tig  = lane & 3;

    const size_t hoff = (size_t)h * HD_;
    const __half* Qg = Q + ((size_t)(b*S_ + qt*64)) * D_ + hoff;

    const __half2 sc2 = __floats2half2_rn(0.125f, 0.125f);
    for (int i = tid; i < 512; i += 128) {
        int r = i >> 3, c = (i & 7) * 8;
        uint4 u = *(const uint4*)(Qg + (size_t)r * D_ + c);
        __half2* hp = (__half2*)&u;
#pragma unroll
        for (int t = 0; t < 4; t++) hp[t] = __hmul2(hp[t], sc2);
        *(uint4*)&Qs[r*ATS + c] = u;
    }
    __syncthreads();

    const unsigned qb = (unsigned)__cvta_generic_to_shared(Qs);
    const unsigned kb = (unsigned)__cvta_generic_to_shared(Ks);
    const unsigned vb = (unsigned)__cvta_generic_to_shared(Vs);
    const int lrow = lane & 15;
    const int lcb  = (lane >> 4) * 8;

    unsigned aQ[4][4];
#pragma unroll
    for (int t = 0; t < 4; t++) {
        unsigned ad = qb + (unsigned)(((w*16 + lrow) * ATS + t*16 + lcb) * 2);
        asm volatile("ldmatrix.sync.aligned.m8n8.x4.shared.b16 {%0,%1,%2,%3}, [%4];"
                     : "=r"(aQ[t][0]), "=r"(aQ[t][1]), "=r"(aQ[t][2]), "=r"(aQ[t][3])
                     : "r"(ad));
    }

    float oacc[8][4];
#pragma unroll
    for (int j = 0; j < 8; j++)
#pragma unroll
        for (int c = 0; c < 4; c++) oacc[j][c] = 0.f;
    float m0 = -INFINITY, m1 = -INFINITY, l0 = 0.f, l1 = 0.f;

    const int r0l = w*16 + gid;
    const int r1l = r0l + 8;

    for (int kt = 0; kt <= qt; kt++) {
        __syncthreads();
        const __half* Kg = K + ((size_t)(b*S_ + kt*64)) * D_ + hoff;
        const __half* Vg = V + ((size_t)(b*S_ + kt*64)) * D_ + hoff;
        for (int i = tid; i < 1024; i += 128) {
            int r = (i >> 3) & 63, c = (i & 7) * 8;
            if (i < 512)
                *(uint4*)&Ks[r*ATS + c] = *(const uint4*)(Kg + (size_t)r * D_ + c);
            else
                *(uint4*)&Vs[r*ATS + c] = *(const uint4*)(Vg + (size_t)r * D_ + c);
        }
        __syncthreads();

        float sacc[8][4];
#pragma unroll
        for (int j = 0; j < 8; j++)
#pragma unroll
            for (int c = 0; c < 4; c++) sacc[j][c] = 0.f;

#pragma unroll
        for (int t = 0; t < 4; t++) {
#pragma unroll
            for (int jp = 0; jp < 4; jp++) {
                unsigned bk[4];
                unsigned ad = kb + (unsigned)(((jp*16 + lrow) * ATS + t*16 + lcb) * 2);
                asm volatile("ldmatrix.sync.aligned.m8n8.x4.shared.b16 {%0,%1,%2,%3}, [%4];"
                             : "=r"(bk[0]), "=r"(bk[1]), "=r"(bk[2]), "=r"(bk[3])
                             : "r"(ad));
                asm volatile(
                    "mma.sync.aligned.m16n8k16.row.col.f32.f16.f16.f32 "
                    "{%0,%1,%2,%3},{%4,%5,%6,%7},{%8,%9},{%0,%1,%2,%3};"
                    : "+f"(sacc[2*jp][0]), "+f"(sacc[2*jp][1]),
                      "+f"(sacc[2*jp][2]), "+f"(sacc[2*jp][3])
                    : "r"(aQ[t][0]), "r"(aQ[t][1]), "r"(aQ[t][2]), "r"(aQ[t][3]),
                      "r"(bk[0]), "r"(bk[2]));
                asm volatile(
                    "mma.sync.aligned.m16n8k16.row.col.f32.f16.f16.f32 "
                    "{%0,%1,%2,%3},{%4,%5,%6,%7},{%8,%9},{%0,%1,%2,%3};"
                    : "+f"(sacc[2*jp+1][0]), "+f"(sacc[2*jp+1][1]),
                      "+f"(sacc[2*jp+1][2]), "+f"(sacc[2*jp+1][3])
                    : "r"(aQ[t][0]), "r"(aQ[t][1]), "r"(aQ[t][2]), "r"(aQ[t][3]),
                      "r"(bk[1]), "r"(bk[3]));
            }
        }

        if (kt == qt) {
#pragma unroll
            for (int j = 0; j < 8; j++) {
                int c0 = j*8 + tig*2;
                if (c0     > r0l) sacc[j][0] = -INFINITY;
                if (c0 + 1 > r0l) sacc[j][1] = -INFINITY;
                if (c0     > r1l) sacc[j][2] = -INFINITY;
                if (c0 + 1 > r1l) sacc[j][3] = -INFINITY;
            }
        }

        float mx0 = -INFINITY, mx1 = -INFINITY;
#pragma unroll
        for (int j = 0; j < 8; j++) {
            mx0 = fmaxf(mx0, fmaxf(sacc[j][0], sacc[j][1]));
            mx1 = fmaxf(mx1, fmaxf(sacc[j][2], sacc[j][3]));
        }
#pragma unroll
        for (int o = 1; o <= 2; o <<= 1) {
            mx0 = fmaxf(mx0, __shfl_xor_sync(0xffffffffu, mx0, o));
            mx1 = fmaxf(mx1, __shfl_xor_sync(0xffffffffu, mx1, o));
        }
        float nm0 = fmaxf(m0, mx0), nm1 = fmaxf(m1, mx1);
        float corr0 = __expf(m0 - nm0), corr1 = __expf(m1 - nm1);

        unsigned pa0[8], pa1[8];
        float sum0 = 0.f, sum1 = 0.f;
#pragma unroll
        for (int j = 0; j < 8; j++) {
            float p00 = __expf(sacc[j][0] - nm0);
            float p01 = __expf(sacc[j][1] - nm0);
            float p10 = __expf(sacc[j][2] - nm1);
            float p11 = __expf(sacc[j][3] - nm1);
            sum0 += p00 + p01;
            sum1 += p10 + p11;
            __half2 h0 = __floats2half2_rn(p00, p01);
            __half2 h1 = __floats2half2_rn(p10, p11);
            pa0[j] = *(unsigned*)&h0;
            pa1[j] = *(unsigned*)&h1;
        }
#pragma unroll
        for (int o = 1; o <= 2; o <<= 1) {
            sum0 += __shfl_xor_sync(0xffffffffu, sum0, o);
            sum1 += __shfl_xor_sync(0xffffffffu, sum1, o);
        }
        l0 = l0 * corr0 + sum0;
        l1 = l1 * corr1 + sum1;
        m0 = nm0; m1 = nm1;
#pragma unroll
        for (int j = 0; j < 8; j++) {
            oacc[j][0] *= corr0; oacc[j][1] *= corr0;
            oacc[j][2] *= corr1; oacc[j][3] *= corr1;
        }

#pragma unroll
        for (int kc = 0; kc < 4; kc++) {
            unsigned a0 = pa0[2*kc], a1 = pa1[2*kc], a2 = pa0[2*kc+1], a3 = pa1[2*kc+1];
#pragma unroll
            for (int dp = 0; dp < 4; dp++) {
                unsigned bv[4];
                unsigned ad = vb + (unsigned)(((kc*16 + lrow) * ATS + dp*16 + lcb) * 2);
                asm volatile("ldmatrix.sync.aligned.m8n8.x4.trans.shared.b16 {%0,%1,%2,%3}, [%4];"
                             : "=r"(bv[0]), "=r"(bv[1]), "=r"(bv[2]), "=r"(bv[3])
                             : "r"(ad));
                asm volatile(
                    "mma.sync.aligned.m16n8k16.row.col.f32.f16.f16.f32 "
                    "{%0,%1,%2,%3},{%4,%5,%6,%7},{%8,%9},{%0,%1,%2,%3};"
                    : "+f"(oacc[2*dp][0]), "+f"(oacc[2*dp][1]),
                      "+f"(oacc[2*dp][2]), "+f"(oacc[2*dp][3])
                    : "r"(a0), "r"(a1), "r"(a2), "r"(a3),
                      "r"(bv[0]), "r"(bv[1]));
                asm volatile(
                    "mma.sync.aligned.m16n8k16.row.col.f32.f16.f16.f32 "
                    "{%0,%1,%2,%3},{%4,%5,%6,%7},{%8,%9},{%0,%1,%2,%3};"
                    : "+f"(oacc[2*dp+1][0]), "+f"(oacc[2*dp+1][1]),
                      "+f"(oacc[2*dp+1][2]), "+f"(oacc[2*dp+1][3])
                    : "r"(a0), "r"(a1), "r"(a2), "r"(a3),
                      "r"(bv[2]), "r"(bv[3]));
            }
        }
    }

    float inv0 = 1.f / l0, inv1 = 1.f / l1;
    size_t row0 = ((size_t)(b*S_ + qt*64 + r0l)) * D_ + hoff;
    size_t row1 = ((size_t)(b*S_ + qt*64 + r1l)) * D_ + hoff;
#pragma unroll
    for (int j = 0; j < 8; j++) {
        int c = j*8 + tig*2;
        __half2 o0 = __floats2half2_rn(oacc[j][0]*inv0, oacc[j][1]*inv0);
        __half2 o1 = __floats2half2_rn(oacc[j][2]*inv1, oacc[j][3]*inv1);
        *(__half2*)(O + row0 + c) = o0;
        *(__half2*)(O + row1 + c) = o1;
    }
}

// ---------------- LayerNorm over D (f32 in, f16 out) ------------------------
__global__ void ln_kernel(const float* __restrict__ H,
                          const float* __restrict__ g,
                          const float* __restrict__ bb,
                          __half* __restrict__ out)
{
    int row = blockIdx.x;
    const float* h = H + (size_t)row * D_;
    __shared__ float red[256];
    int tid = threadIdx.x;

    float s = 0.f;
    for (int i = tid; i < D_; i += 256) s += h[i];
    red[tid] = s; __syncthreads();
    for (int o = 128; o; o >>= 1) { if (tid < o) red[tid] += red[tid+o]; __syncthreads(); }
    float mu = red[0] / (float)D_;
    __syncthreads();

    float v = 0.f;
    for (int i = tid; i < D_; i += 256) { float d = h[i] - mu; v += d*d; }
    red[tid] = v; __syncthreads();
    for (int o = 128; o; o >>= 1) { if (tid < o) red[tid] += red[tid+o]; __syncthreads(); }
    float rstd = rsqrtf(red[0] / (float)D_ + 1e-5f);

    __half* o2 = out + (size_t)row * D_;
    for (int i = tid; i < D_; i += 256)
        o2[i] = __float2half((h[i] - mu) * rstd * g[i] + bb[i]);
}

// ---------------- loss from per-block partials -------------------------------
__global__ void loss_partials_kernel(const float* __restrict__ logits,
                                     const int* __restrict__ targets,
                                     const float* __restrict__ pmax,
                                     const float* __restrict__ psum,
                                     float* __restrict__ rowloss)
{
    int row = blockIdx.x;
    int tid = threadIdx.x;
    __shared__ float rm[128], rs[128];

    float m = NEG_, s = 0.f;
    for (int j = tid; j < NBLK_; j += 128) {
        float m2 = pmax[(size_t)row * NBLK_ + j];
        float s2 = psum[(size_t)row * NBLK_ + j];
        float mm = fmaxf(m, m2);
        s = s * __expf(m - mm) + s2 * __expf(m2 - mm);
        m = mm;
    }
    rm[tid] = m; rs[tid] = s; __syncthreads();
    for (int o = 64; o; o >>= 1) {
        if (tid < o) {
            float m1 = rm[tid], s1 = rs[tid];
            float m2 = rm[tid+o], s2 = rs[tid+o];
            float mm = fmaxf(m1, m2);
            rm[tid] = mm;
            rs[tid] = s1 * __expf(m1 - mm) + s2 * __expf(m2 - mm);
        }
        __syncthreads();
    }
    if (tid == 0)
        rowloss[row] = -(logits[(size_t)row * V_ + targets[row]] - rm[0] - logf(rs[0]));
}

__global__ void loss_reduce_kernel(const float* __restrict__ rowloss,
                                   float* __restrict__ out)
{
    __shared__ float red[256];
    int tid = threadIdx.x;
    float s = 0.f;
    for (int i = tid; i < T_; i += 256) s += rowloss[i];
    red[tid] = s; __syncthreads();
    for (int o = 128; o; o >>= 1) { if (tid < o) red[tid] += red[tid+o]; __syncthreads(); }
    if (tid == 0) out[0] = red[0] / (float)T_;
}

// ---------------- launcher ---------------------------------------------------
extern "C" void kernel_launch(void* const* d_in, const int* in_sizes, int n_in,
                              void* d_out, int out_size)
{
    const int*   inputs  = (const int*)  d_in[0];
    const int*   targets = (const int*)  d_in[1];
    const float* wte     = (const float*)d_in[2];
    const float* wq      = (const float*)d_in[3];
    const float* bq      = (const float*)d_in[4];
    const float* wk      = (const float*)d_in[5];
    const float* bk      = (const float*)d_in[6];
    const float* wv      = (const float*)d_in[7];
    const float* bv      = (const float*)d_in[8];
    const float* wo      = (const float*)d_in[9];
    const float* bo      = (const float*)d_in[10];
    const float* w1      = (const float*)d_in[11];
    const float* b1      = (const float*)d_in[12];
    const float* w2      = (const float*)d_in[13];
    const float* b2      = (const float*)d_in[14];
    const float* ln_g    = (const float*)d_in[15];
    const float* ln_b    = (const float*)d_in[16];
    const float* w_out   = (const float*)d_in[17];
    const float* b_out   = (const float*)d_in[18];
    float* out = (float*)d_out;

    __half *x,*q,*k,*v,*ctx,*ao,*h1,*hn,*w;
    float *h2,*rowloss,*pmax,*psum,*bqkv;
    cudaGetSymbolAddress((void**)&x,   g_x);
    cudaGetSymbolAddress((void**)&q,   g_q);
    cudaGetSymbolAddress((void**)&k,   g_k);
    cudaGetSymbolAddress((void**)&v,   g_v);
    cudaGetSymbolAddress((void**)&ctx, g_ctx);
    cudaGetSymbolAddress((void**)&ao,  g_ao);
    cudaGetSymbolAddress((void**)&h1,  g_h1);
    cudaGetSymbolAddress((void**)&h2,  g_h2);
    cudaGetSymbolAddress((void**)&hn,  g_hn);
    cudaGetSymbolAddress((void**)&rowloss, g_rowloss);
    cudaGetSymbolAddress((void**)&pmax, g_pmax);
    cudaGetSymbolAddress((void**)&psum, g_psum);
    cudaGetSymbolAddress((void**)&bqkv, g_bqkv);
    cudaGetSymbolAddress((void**)&w,   g_w);

    const int SMEM_GEMM  = 3 * STGB;
    const int SMEM_GEMM6 = 3 * STG6B;   // 87552
    cudaFuncSetAttribute(hgemm_kernel, cudaFuncAttributeMaxDynamicSharedMemorySize, SMEM_GEMM);
    cudaFuncSetAttribute(hgemm256_kernel, cudaFuncAttributeMaxDynamicSharedMemorySize, SMEM_GEMM6);

    // 0. fused weight conversion (single launch)
    convert_all_kernel<<<(int)((CN5 + 255) / 256), 256>>>(
        wq, wk, wv, wo, w1, w2, w_out, bq, bk, bv, w, bqkv);

    // 1. embedding + positional encoding (fp16)
    embed_kernel<<<(T_*D_)/256, 256>>>(inputs, wte, x);

    // 2. fused Q,K,V projection (one GEMM, split epilogue)
    hgemm_kernel<<<dim3(T_/128, 3*D_/128), 256, SMEM_GEMM>>>(
        x, w+OFF_WQKV, bqkv, 0, q, k, v, T_, 3*D_, D_, 3*D_, 0, 2);

    // 3. causal multi-head attention (heavy tiles first)
    attn_tc_kernel<<<dim3(S_/64, B_*NH_), 128>>>(q, k, v, ctx);

    // 4. output projection -> fp16 ao
    dim3 gDD(T_/128, D_/128);
    hgemm_kernel<<<gDD, 256, SMEM_GEMM>>>(
        ctx, w+OFF_WO, bo, ao, 0,0,0, T_, D_, D_, D_, 0, 1);

    // 5. FFN (h1 fp16 + relu; h2 fp32 for LN)
    hgemm_kernel<<<dim3(T_/128, HID_/128), 256, SMEM_GEMM>>>(
        ao, w+OFF_W1, b1, h1, 0,0,0, T_, HID_, D_, HID_, 1, 1);
    hgemm_kernel<<<gDD, 256, SMEM_GEMM>>>(
        h1, w+OFF_W2, b2, h2, 0,0,0, T_, D_, HID_, D_, 0, 0);

    // 6. LayerNorm (fp32 in -> fp16 hn)
    ln_kernel<<<T_, 256>>>(h2, ln_g, ln_b, hn);

    // 7. vocab projection (BM=256) -> fp32 logits + fused softmax partials
    hgemm256_kernel<<<dim3(T_/256, NBLK_), 256, SMEM_GEMM6>>>(
        hn, w+OFF_WOUT, b_out, out, pmax, psum, NBLK_, T_, V_, D_, VP2_);

    // 8. cross-entropy loss from partials
    loss_partials_kernel<<<T_, 128>>>(out, targets, pmax, psum, rowloss);
    if (out_size > T_ * V_)
        loss_reduce_kernel<<<1, 256>>>(rowloss, out + (size_t)T_ * V_);
}

// round 14
// speedup vs baseline: 1.0019x; 1.0019x over previous
#include <cuda_runtime.h>
#include <cuda_fp16.h>
#include <math.h>

#define V_   50257
#define VP2_ 50304            // V padded to multiple of 128 (half scratch row stride)
#define NBLK_ 393             // vocab n-tiles of 128
#define D_   768
#define S_   2048
#define B_   2
#define HID_ 2048
#define NH_  12
#define HD_  64
#define T_   (B_*S_)   // 4096 tokens
#define NEG_ -1e30f

// ---------------- scratch (device globals; no allocation allowed) ----------
__device__ __half g_x  [T_*D_];
__device__ __half g_q  [T_*D_];
__device__ __half g_k  [T_*D_];
__device__ __half g_v  [T_*D_];
__device__ __half g_ctx[T_*D_];
__device__ __half g_ao [T_*D_];
__device__ __half g_h1 [T_*HID_];
__device__ float  g_h2 [T_*D_];
__device__ __half g_hn [T_*D_];
__device__ float  g_rowloss[T_];
__device__ float  g_pmax[T_*NBLK_];
__device__ float  g_psum[T_*NBLK_];
__device__ float  g_bqkv[3*D_];
// fp16 weight scratch: wqkv | wo | w1 | w2 | w_out(padded)  — CONTIGUOUS regions
#define OFF_WQKV 0
#define OFF_WO   (OFF_WQKV + D_*3*D_)
#define OFF_W1   (OFF_WO + D_*D_)
#define OFF_W2   (OFF_W1 + D_*HID_)
#define OFF_WOUT (OFF_W2 + HID_*D_)
#define W_TOTAL  (OFF_WOUT + D_*VP2_ + 64)
__device__ __half g_w[W_TOTAL];

// ---------------- fused weight conversion (ONE launch) -----------------------
#define CN0 221184L
#define CN1 (CN0 + 73728L)
#define CN2 (CN1 + 196608L)
#define CN3 (CN2 + 196608L)
#define CN4 (CN3 + 4829184L)
#define CN5 (CN4 + 288L)

__device__ __forceinline__ void cvt8(const float* __restrict__ src, __half* dst) {
    float4 a = *(const float4*)src;
    float4 b = *(const float4*)(src + 4);
    __half h[8] = { __float2half(a.x), __float2half(a.y), __float2half(a.z), __float2half(a.w),
                    __float2half(b.x), __float2half(b.y), __float2half(b.z), __float2half(b.w) };
    *(uint4*)dst = *(const uint4*)h;
}

__global__ void convert_all_kernel(const float* __restrict__ wq, const float* __restrict__ wk,
                                   const float* __restrict__ wv, const float* __restrict__ wo,
                                   const float* __restrict__ w1, const float* __restrict__ w2,
                                   const float* __restrict__ wout,
                                   const float* __restrict__ bq, const float* __restrict__ bk,
                                   const float* __restrict__ bv,
                                   __half* __restrict__ w, float* __restrict__ bqkv)
{
    long j = (long)blockIdx.x * blockDim.x + threadIdx.x;
    if (j >= CN5) return;
    if (j < CN0) {
        long off = j * 8;
        int r = (int)(off / (3*D_)), rem = (int)(off % (3*D_));
        int sel = rem / D_, c = rem % D_;
        const float* src = (sel == 0 ? wq : sel == 1 ? wk : wv) + (size_t)r * D_ + c;
        cvt8(src, w + off);
    } else if (j < CN1) {
        cvt8(wo + (j - CN0) * 8, w + j * 8);
    } else if (j < CN2) {
        cvt8(w1 + (j - CN1) * 8, w + j * 8);
    } else if (j < CN3) {
        cvt8(w2 + (j - CN2) * 8, w + j * 8);
    } else if (j < CN4) {
        long jj = j - CN3;
        int r = (int)(jj / (VP2_/8));
        int c = (int)(jj % (VP2_/8)) * 8;
        const float* src = wout + (size_t)r * V_ + c;
        __half tmp[8];
#pragma unroll
        for (int e = 0; e < 8; e++)
            tmp[e] = (c + e < V_) ? __float2half(__ldg(src + e)) : __half(0.f);
        *(uint4*)(w + j * 8) = *(const uint4*)tmp;
    } else {
        int i = (int)(j - CN4) * 8;
#pragma unroll
        for (int e = 0; e < 8; e++) {
            int idx = i + e;
            int sel = idx / D_, c = idx - sel * D_;
            bqkv[idx] = (sel == 0 ? bq : sel == 1 ? bk : bv)[c];
        }
    }
}

// ---------------- embedding + sinusoidal positional encoding ---------------
__global__ void embed_kernel(const int* __restrict__ inputs,
                             const float* __restrict__ wte,
                             __half* __restrict__ x)
{
    int idx = blockIdx.x * blockDim.x + threadIdx.x;
    if (idx >= T_*D_) return;
    int t = idx / D_;
    int d = idx - t * D_;
    int s = t & (S_-1);
    int tok = inputs[t];
    int i2 = (d >> 1) * 2;
    float div = expf((float)(-i2) * (logf(10000.0f) / (float)D_));
    float ang = (float)s * div;
    float pe = (d & 1) ? cosf(ang) : sinf(ang);
    x[idx] = __float2half(wte[(size_t)tok * D_ + d] + pe);
}

// ---------------- fp16 tensor-core GEMM (BM=128), 3-stage cp.async -----------
// modes: 0 = f32 out, 1 = f16 out, 2 = qkv split f16 out
#define AST2 40
#define BST2 136
#define ASTB (128*AST2*2)
#define STGB (ASTB + 32*BST2*2)

__global__ __launch_bounds__(256, 2)
void hgemm_kernel(const __half* __restrict__ A, const __half* __restrict__ W,
                  const float* __restrict__ bias, void* __restrict__ Cout,
                  __half* __restrict__ dq, __half* __restrict__ dk, __half* __restrict__ dv,
                  int M, int N, int K, int ldW, int relu, int mode)
{
    extern __shared__ char smc[];
    const int tid  = threadIdx.x;
    const int warp = tid >> 5;
    const int lane = tid & 31;
    const int gid  = lane >> 2;
    const int tig  = lane & 3;
    const int wm   = warp >> 2;
    const int wn   = warp & 3;
    const int m0 = blockIdx.x * 128;
    const int n0 = blockIdx.y * 128;
    const unsigned smem0 = (unsigned)__cvta_generic_to_shared(smc);

    float acc[4][4][4];
#pragma unroll
    for (int i = 0; i < 4; i++)
#pragma unroll
        for (int j = 0; j < 4; j++)
#pragma unroll
            for (int c = 0; c < 4; c++) acc[i][j][c] = 0.f;

    const int nk = K >> 5;

    auto load_stage = [&](int i) {
        unsigned sa = smem0 + (i % 3) * STGB;
        unsigned sb = sa + ASTB;
        const __half* Ab = A + (size_t)m0 * K + i * 32;
        const __half* Bb = W + (size_t)(i * 32) * ldW + n0;
#pragma unroll
        for (int t = 0; t < 2; t++) {
            int slot = t * 256 + tid;
            int r = slot >> 2, c = (slot & 3) * 8;
            asm volatile("cp.async.cg.shared.global [%0], [%1], 16;"
                         :: "r"(sa + (r * AST2 + c) * 2), "l"(Ab + (size_t)r * K + c));
        }
#pragma unroll
        for (int t = 0; t < 2; t++) {
            int slot = t * 256 + tid;
            int r = slot >> 4, c = (slot & 15) * 8;
            asm volatile("cp.async.cg.shared.global [%0], [%1], 16;"
                         :: "r"(sb + (r * BST2 + c) * 2), "l"(Bb + (size_t)r * ldW + c));
        }
        asm volatile("cp.async.commit_group;");
    };

    load_stage(0);
    load_stage(1);
    asm volatile("cp.async.wait_group 1;");
    __syncthreads();

    const int arow = lane & 15;
    const int acol = (lane >> 4) * 8;

    for (int i = 0; i < nk; i++) {
        unsigned sa = smem0 + (i % 3) * STGB;
        unsigned sb = sa + ASTB;

        if (i + 2 < nk) load_stage(i + 2);
        else            asm volatile("cp.async.commit_group;");

#pragma unroll
        for (int kk = 0; kk < 32; kk += 16) {
            unsigned af[4][4], bf[4][2];
#pragma unroll
            for (int mi = 0; mi < 4; mi++) {
                unsigned ad = sa + ((wm * 64 + mi * 16 + arow) * AST2 + kk + acol) * 2;
                asm volatile("ldmatrix.sync.aligned.m8n8.x4.shared.b16 {%0,%1,%2,%3}, [%4];"
                             : "=r"(af[mi][0]), "=r"(af[mi][1]),
                               "=r"(af[mi][2]), "=r"(af[mi][3]) : "r"(ad));
            }
#pragma unroll
            for (int nh = 0; nh < 2; nh++) {
                unsigned bd = sb + ((kk + arow) * BST2 + wn * 32 + nh * 16 + acol) * 2;
                asm volatile("ldmatrix.sync.aligned.m8n8.x4.trans.shared.b16 {%0,%1,%2,%3}, [%4];"
                             : "=r"(bf[2*nh][0]), "=r"(bf[2*nh][1]),
                               "=r"(bf[2*nh+1][0]), "=r"(bf[2*nh+1][1]) : "r"(bd));
            }
#pragma unroll
            for (int mi = 0; mi < 4; mi++)
#pragma unroll
                for (int ni = 0; ni < 4; ni++) {
                    asm volatile(
                        "mma.sync.aligned.m16n8k16.row.col.f32.f16.f16.f32 "
                        "{%0,%1,%2,%3},{%4,%5,%6,%7},{%8,%9},{%0,%1,%2,%3};"
                        : "+f"(acc[mi][ni][0]), "+f"(acc[mi][ni][1]),
                          "+f"(acc[mi][ni][2]), "+f"(acc[mi][ni][3])
                        : "r"(af[mi][0]), "r"(af[mi][1]),
                          "r"(af[mi][2]), "r"(af[mi][3]),
                          "r"(bf[ni][0]), "r"(bf[ni][1]));
                }
        }

        asm volatile("cp.async.wait_group 1;");
        __syncthreads();
    }

    __half* qdst = 0; int qcol0 = 0;
    if (mode == 2) {
        int sel = n0 / D_;
        qdst  = (sel == 0 ? dq : sel == 1 ? dk : dv);
        qcol0 = n0 - sel * D_;
    }

#pragma unroll
    for (int mi = 0; mi < 4; mi++) {
        int r = m0 + wm * 64 + mi * 16 + gid;
#pragma unroll
        for (int ni = 0; ni < 4; ni++) {
            int cc = n0 + wn * 32 + ni * 8 + tig * 2;
            float b0 = bias[cc], b1 = bias[cc + 1];
            float v0 = acc[mi][ni][0] + b0;
            float v1 = acc[mi][ni][1] + b1;
            float v2 = acc[mi][ni][2] + b0;
            float v3 = acc[mi][ni][3] + b1;
            if (relu) {
                v0 = fmaxf(v0, 0.f); v1 = fmaxf(v1, 0.f);
                v2 = fmaxf(v2, 0.f); v3 = fmaxf(v3, 0.f);
            }
            if (mode == 1) {
                __half2 h0 = __floats2half2_rn(v0, v1);
                __half2 h1 = __floats2half2_rn(v2, v3);
                *(__half2*)((__half*)Cout + (size_t)r * N + cc)       = h0;
                *(__half2*)((__half*)Cout + (size_t)(r + 8) * N + cc) = h1;
            } else if (mode == 2) {
                int lc = qcol0 + (cc - n0);
                __half2 h0 = __floats2half2_rn(v0, v1);
                __half2 h1 = __floats2half2_rn(v2, v3);
                *(__half2*)(qdst + (size_t)r * D_ + lc)       = h0;
                *(__half2*)(qdst + (size_t)(r + 8) * D_ + lc) = h1;
            } else {
                float* C = (float*)Cout;
                C[(size_t)r * N + cc]           = v0;
                C[(size_t)r * N + cc + 1]       = v1;
                C[(size_t)(r + 8) * N + cc]     = v2;
                C[(size_t)(r + 8) * N + cc + 1] = v3;
            }
        }
    }
}

// ---------------- fp16 GEMM BM=256 x BN=128 (vocab + loss partials) ----------
// 8 warps as 4x2, warp tile 64x64: 32 MMA : 8 LDSM per k-step. 1 CTA/SM.
#define A6STB (256*AST2*2)                 // 20480 B
#define STG6B (A6STB + 32*BST2*2)          // 29184 B per stage

__global__ __launch_bounds__(256, 1)
void hgemm256_kernel(const __half* __restrict__ A, const __half* __restrict__ W,
                     const float* __restrict__ bias, float* __restrict__ C,
                     float* __restrict__ pmax, float* __restrict__ psum, int nblk,
                     int M, int N, int K, int ldW)
{
    extern __shared__ char smc[];
    const int tid  = threadIdx.x;
    const int warp = tid >> 5;
    const int lane = tid & 31;
    const int gid  = lane >> 2;
    const int tig  = lane & 3;
    const int wm   = warp >> 1;      // 0..3 (64-row slices)
    const int wn   = warp & 1;       // 0..1 (64-col slices)
    const int m0 = blockIdx.x * 256;
    const int n0 = blockIdx.y * 128;
    const unsigned smem0 = (unsigned)__cvta_generic_to_shared(smc);

    float acc[4][8][4];
#pragma unroll
    for (int i = 0; i < 4; i++)
#pragma unroll
        for (int j = 0; j < 8; j++)
#pragma unroll
            for (int c = 0; c < 4; c++) acc[i][j][c] = 0.f;

    const int nk = K >> 5;

    auto load_stage = [&](int i) {
        unsigned sa = smem0 + (i % 3) * STG6B;
        unsigned sb = sa + A6STB;
        const __half* Ab = A + (size_t)m0 * K + i * 32;
        const __half* Bb = W + (size_t)(i * 32) * ldW + n0;
#pragma unroll
        for (int t = 0; t < 4; t++) {
            int slot = t * 256 + tid;
            int r = slot >> 2, c = (slot & 3) * 8;
            asm volatile("cp.async.cg.shared.global [%0], [%1], 16;"
                         :: "r"(sa + (r * AST2 + c) * 2), "l"(Ab + (size_t)r * K + c));
        }
#pragma unroll
        for (int t = 0; t < 2; t++) {
            int slot = t * 256 + tid;
            int r = slot >> 4, c = (slot & 15) * 8;
            asm volatile("cp.async.cg.shared.global [%0], [%1], 16;"
                         :: "r"(sb + (r * BST2 + c) * 2), "l"(Bb + (size_t)r * ldW + c));
        }
        asm volatile("cp.async.commit_group;");
    };

    load_stage(0);
    load_stage(1);
    asm volatile("cp.async.wait_group 1;");
    __syncthreads();

    const int arow = lane & 15;
    const int acol = (lane >> 4) * 8;

    for (int i = 0; i < nk; i++) {
        unsigned sa = smem0 + (i % 3) * STG6B;
        unsigned sb = sa + A6STB;

        if (i + 2 < nk) load_stage(i + 2);
        else            asm volatile("cp.async.commit_group;");

#pragma unroll
        for (int kk = 0; kk < 32; kk += 16) {
            unsigned af[4][4], bf[8][2];
#pragma unroll
            for (int mi = 0; mi < 4; mi++) {
                unsigned ad = sa + ((wm * 64 + mi * 16 + arow) * AST2 + kk + acol) * 2;
                asm volatile("ldmatrix.sync.aligned.m8n8.x4.shared.b16 {%0,%1,%2,%3}, [%4];"
                             : "=r"(af[mi][0]), "=r"(af[mi][1]),
                               "=r"(af[mi][2]), "=r"(af[mi][3]) : "r"(ad));
            }
#pragma unroll
            for (int nh = 0; nh < 4; nh++) {
                unsigned bd = sb + ((kk + arow) * BST2 + wn * 64 + nh * 16 + acol) * 2;
                asm volatile("ldmatrix.sync.aligned.m8n8.x4.trans.shared.b16 {%0,%1,%2,%3}, [%4];"
                             : "=r"(bf[2*nh][0]), "=r"(bf[2*nh][1]),
                               "=r"(bf[2*nh+1][0]), "=r"(bf[2*nh+1][1]) : "r"(bd));
            }
#pragma unroll
            for (int mi = 0; mi < 4; mi++)
#pragma unroll
                for (int ni = 0; ni < 8; ni++) {
                    asm volatile(
                        "mma.sync.aligned.m16n8k16.row.col.f32.f16.f16.f32 "
                        "{%0,%1,%2,%3},{%4,%5,%6,%7},{%8,%9},{%0,%1,%2,%3};"
                        : "+f"(acc[mi][ni][0]), "+f"(acc[mi][ni][1]),
                          "+f"(acc[mi][ni][2]), "+f"(acc[mi][ni][3])
                        : "r"(af[mi][0]), "r"(af[mi][1]),
                          "r"(af[mi][2]), "r"(af[mi][3]),
                          "r"(bf[ni][0]), "r"(bf[ni][1]));
                }
        }

        asm volatile("cp.async.wait_group 1;");
        __syncthreads();
    }

    float* red = (float*)smc;   // [256 rows][2 wn][2] = 4KB (pipeline done)

#pragma unroll
    for (int mi = 0; mi < 4; mi++) {
        int rl = wm * 64 + mi * 16 + gid;   // local row (half 0); +8 for half 1
        int r  = m0 + rl;
        float mA = NEG_, sA = 0.f, mB = NEG_, sB = 0.f;
#pragma unroll
        for (int ni = 0; ni < 8; ni++) {
            int cc = n0 + wn * 64 + ni * 8 + tig * 2;
            bool full = (cc + 1 < N);
            bool any  = (cc < N);
            float b0 = any  ? bias[cc]     : 0.f;
            float b1 = full ? bias[cc + 1] : 0.f;
            float v0 = acc[mi][ni][0] + b0;
            float v1 = acc[mi][ni][1] + b1;
            float v2 = acc[mi][ni][2] + b0;
            float v3 = acc[mi][ni][3] + b1;
            if (any) {
                asm volatile("st.global.cs.f32 [%0], %1;" :: "l"(C + (size_t)r * N + cc), "f"(v0));
                asm volatile("st.global.cs.f32 [%0], %1;" :: "l"(C + (size_t)(r + 8) * N + cc), "f"(v2));
                if (v0 > mA) { sA = sA * __expf(mA - v0) + 1.f; mA = v0; }
                else         { sA += __expf(v0 - mA); }
                if (v2 > mB) { sB = sB * __expf(mB - v2) + 1.f; mB = v2; }
                else         { sB += __expf(v2 - mB); }
            }
            if (full) {
                asm volatile("st.global.cs.f32 [%0], %1;" :: "l"(C + (size_t)r * N + cc + 1), "f"(v1));
                asm volatile("st.global.cs.f32 [%0], %1;" :: "l"(C + (size_t)(r + 8) * N + cc + 1), "f"(v3));
                if (v1 > mA) { sA = sA * __expf(mA - v1) + 1.f; mA = v1; }
                else         { sA += __expf(v1 - mA); }
                if (v3 > mB) { sB = sB * __expf(mB - v3) + 1.f; mB = v3; }
                else         { sB += __expf(v3 - mB); }
            }
        }
        // quad reduce over tig lanes
#pragma unroll
        for (int o = 1; o <= 2; o <<= 1) {
            float m2 = __shfl_xor_sync(0xffffffffu, mA, o);
            float s2 = __shfl_xor_sync(0xffffffffu, sA, o);
            float mm = fmaxf(mA, m2);
            sA = sA * __expf(mA - mm) + s2 * __expf(m2 - mm);
            mA = mm;
            m2 = __shfl_xor_sync(0xffffffffu, mB, o);
            s2 = __shfl_xor_sync(0xffffffffu, sB, o);
            mm = fmaxf(mB, m2);
            sB = sB * __expf(mB - mm) + s2 * __expf(m2 - mm);
            mB = mm;
        }
        if (tig == 0) {
            red[((rl    ) * 2 + wn) * 2 + 0] = mA;
            red[((rl    ) * 2 + wn) * 2 + 1] = sA;
            red[((rl + 8) * 2 + wn) * 2 + 0] = mB;
            red[((rl + 8) * 2 + wn) * 2 + 1] = sB;
        }
    }

    __syncthreads();
    {
        float m = NEG_, s = 0.f;
#pragma unroll
        for (int wnn = 0; wnn < 2; wnn++) {
            float m2 = red[(tid * 2 + wnn) * 2 + 0];
            float s2 = red[(tid * 2 + wnn) * 2 + 1];
            float mm = fmaxf(m, m2);
            s = s * __expf(m - mm) + s2 * __expf(m2 - mm);
            m = mm;
        }
        pmax[(size_t)(m0 + tid) * nblk + blockIdx.y] = m;
        psum[(size_t)(m0 + tid) * nblk + blockIdx.y] = s;
    }
}

// ---------------- tensor-core flash attention (FA2 layout) -------------------
#define ATS 72

__global__ __launch_bounds__(128)
void attn_tc_kernel(const __half* __restrict__ Q, const __half* __restrict__ K,
                    const __half* __restrict__ V, __half* __restrict__ O)
{
    __shared__ __half Qs[64*ATS];
    __shared__ __half Ks[64*ATS];
    __shared__ __half Vs[64*ATS];

    const int qt = (int)gridDim.x - 1 - (int)blockIdx.x;   // heavy tiles first
    const int bh = blockIdx.y;
    const int b  = bh / NH_;
    const int h  = bh - b * NH_;

    const int tid  = threadIdx.x;
    const int w    = tid >> 5;
    const int lane = tid & 31;
    const int gid  = lane >> 2;
    const int tig  = lane & 3;

    const size_t hoff = (size_t)h * HD_;
    const __half* Qg = Q + ((size_t)(b*S_ + qt*64)) * D_ + hoff;

    const __half2 sc2 = __floats2half2_rn(0.125f, 0.125f);
    for (int i = tid; i < 512; i += 128) {
        int r = i >> 3, c = (i & 7) * 8;
        uint4 u = *(const uint4*)(Qg + (size_t)r * D_ + c);
        __half2* hp = (__half2*)&u;
#pragma unroll
        for (int t = 0; t < 4; t++) hp[t] = __hmul2(hp[t], sc2);
        *(uint4*)&Qs[r*ATS + c] = u;
    }
    __syncthreads();

    const unsigned qb = (unsigned)__cvta_generic_to_shared(Qs);
    const unsigned kb = (unsigned)__cvta_generic_to_shared(Ks);
    const unsigned vb = (unsigned)__cvta_generic_to_shared(Vs);
    const int lrow = lane & 15;
    const int lcb  = (lane >> 4) * 8;

    unsigned aQ[4][4];
#pragma unroll
    for (int t = 0; t < 4; t++) {
        unsigned ad = qb + (unsigned)(((w*16 + lrow) * ATS + t*16 + lcb) * 2);
        asm volatile("ldmatrix.sync.aligned.m8n8.x4.shared.b16 {%0,%1,%2,%3}, [%4];"
                     : "=r"(aQ[t][0]), "=r"(aQ[t][1]), "=r"(aQ[t][2]), "=r"(aQ[t][3])
                     : "r"(ad));
    }

    float oacc[8][4];
#pragma unroll
    for (int j = 0; j < 8; j++)
#pragma unroll
        for (int c = 0; c < 4; c++) oacc[j][c] = 0.f;
    float m0 = -INFINITY, m1 = -INFINITY, l0 = 0.f, l1 = 0.f;

    const int r0l = w*16 + gid;
    const int r1l = r0l + 8;

    for (int kt = 0; kt <= qt; kt++) {
        __syncthreads();
        const __half* Kg = K + ((size_t)(b*S_ + kt*64)) * D_ + hoff;
        const __half* Vg = V + ((size_t)(b*S_ + kt*64)) * D_ + hoff;
        for (int i = tid; i < 1024; i += 128) {
            int r = (i >> 3) & 63, c = (i & 7) * 8;
            if (i < 512)
                *(uint4*)&Ks[r*ATS + c] = *(const uint4*)(Kg + (size_t)r * D_ + c);
            else
                *(uint4*)&Vs[r*ATS + c] = *(const uint4*)(Vg + (size_t)r * D_ + c);
        }
        __syncthreads();

        float sacc[8][4];
#pragma unroll
        for (int j = 0; j < 8; j++)
#pragma unroll
            for (int c = 0; c < 4; c++) sacc[j][c] = 0.f;

#pragma unroll
        for (int t = 0; t < 4; t++) {
#pragma unroll
            for (int jp = 0; jp < 4; jp++) {
                unsigned bk[4];
                unsigned ad = kb + (unsigned)(((jp*16 + lrow) * ATS + t*16 + lcb) * 2);
                asm volatile("ldmatrix.sync.aligned.m8n8.x4.shared.b16 {%0,%1,%2,%3}, [%4];"
                             : "=r"(bk[0]), "=r"(bk[1]), "=r"(bk[2]), "=r"(bk[3])
                             : "r"(ad));
                asm volatile(
                    "mma.sync.aligned.m16n8k16.row.col.f32.f16.f16.f32 "
                    "{%0,%1,%2,%3},{%4,%5,%6,%7},{%8,%9},{%0,%1,%2,%3};"
                    : "+f"(sacc[2*jp][0]), "+f"(sacc[2*jp][1]),
                      "+f"(sacc[2*jp][2]), "+f"(sacc[2*jp][3])
                    : "r"(aQ[t][0]), "r"(aQ[t][1]), "r"(aQ[t][2]), "r"(aQ[t][3]),
                      "r"(bk[0]), "r"(bk[2]));
                asm volatile(
                    "mma.sync.aligned.m16n8k16.row.col.f32.f16.f16.f32 "
                    "{%0,%1,%2,%3},{%4,%5,%6,%7},{%8,%9},{%0,%1,%2,%3};"
                    : "+f"(sacc[2*jp+1][0]), "+f"(sacc[2*jp+1][1]),
                      "+f"(sacc[2*jp+1][2]), "+f"(sacc[2*jp+1][3])
                    : "r"(aQ[t][0]), "r"(aQ[t][1]), "r"(aQ[t][2]), "r"(aQ[t][3]),
                      "r"(bk[1]), "r"(bk[3]));
            }
        }

        if (kt == qt) {
#pragma unroll
            for (int j = 0; j < 8; j++) {
                int c0 = j*8 + tig*2;
                if (c0     > r0l) sacc[j][0] = -INFINITY;
                if (c0 + 1 > r0l) sacc[j][1] = -INFINITY;
                if (c0     > r1l) sacc[j][2] = -INFINITY;
                if (c0 + 1 > r1l) sacc[j][3] = -INFINITY;
            }
        }

        float mx0 = -INFINITY, mx1 = -INFINITY;
#pragma unroll
        for (int j = 0; j < 8; j++) {
            mx0 = fmaxf(mx0, fmaxf(sacc[j][0], sacc[j][1]));
            mx1 = fmaxf(mx1, fmaxf(sacc[j][2], sacc[j][3]));
        }
#pragma unroll
        for (int o = 1; o <= 2; o <<= 1) {
            mx0 = fmaxf(mx0, __shfl_xor_sync(0xffffffffu, mx0, o));
            mx1 = fmaxf(mx1, __shfl_xor_sync(0xffffffffu, mx1, o));
        }
        float nm0 = fmaxf(m0, mx0), nm1 = fmaxf(m1, mx1);
        float corr0 = __expf(m0 - nm0), corr1 = __expf(m1 - nm1);

        unsigned pa0[8], pa1[8];
        float sum0 = 0.f, sum1 = 0.f;
#pragma unroll
        for (int j = 0; j < 8; j++) {
            float p00 = __expf(sacc[j][0] - nm0);
            float p01 = __expf(sacc[j][1] - nm0);
            float p10 = __expf(sacc[j][2] - nm1);
            float p11 = __expf(sacc[j][3] - nm1);
            sum0 += p00 + p01;
            sum1 += p10 + p11;
            __half2 h0 = __floats2half2_rn(p00, p01);
            __half2 h1 = __floats2half2_rn(p10, p11);
            pa0[j] = *(unsigned*)&h0;
            pa1[j] = *(unsigned*)&h1;
        }
#pragma unroll
        for (int o = 1; o <= 2; o <<= 1) {
            sum0 += __shfl_xor_sync(0xffffffffu, sum0, o);
            sum1 += __shfl_xor_sync(0xffffffffu, sum1, o);
        }
        l0 = l0 * corr0 + sum0;
        l1 = l1 * corr1 + sum1;
        m0 = nm0; m1 = nm1;
#pragma unroll
        for (int j = 0; j < 8; j++) {
            oacc[j][0] *= corr0; oacc[j][1] *= corr0;
            oacc[j][2] *= corr1; oacc[j][3] *= corr1;
        }

#pragma unroll
        for (int kc = 0; kc < 4; kc++) {
            unsigned a0 = pa0[2*kc], a1 = pa1[2*kc], a2 = pa0[2*kc+1], a3 = pa1[2*kc+1];
#pragma unroll
            for (int dp = 0; dp < 4; dp++) {
                unsigned bv[4];
                unsigned ad = vb + (unsigned)(((kc*16 + lrow) * ATS + dp*16 + lcb) * 2);
                asm volatile("ldmatrix.sync.aligned.m8n8.x4.trans.shared.b16 {%0,%1,%2,%3}, [%4];"
                             : "=r"(bv[0]), "=r"(bv[1]), "=r"(bv[2]), "=r"(bv[3])
                             : "r"(ad));
                asm volatile(
                    "mma.sync.aligned.m16n8k16.row.col.f32.f16.f16.f32 "
                    "{%0,%1,%2,%3},{%4,%5,%6,%7},{%8,%9},{%0,%1,%2,%3};"
                    : "+f"(oacc[2*dp][0]), "+f"(oacc[2*dp][1]),
                      "+f"(oacc[2*dp][2]), "+f"(oacc[2*dp][3])
                    : "r"(a0), "r"(a1), "r"(a2), "r"(a3),
                      "r"(bv[0]), "r"(bv[1]));
                asm volatile(
                    "mma.sync.aligned.m16n8k16.row.col.f32.f16.f16.f32 "
                    "{%0,%1,%2,%3},{%4,%5,%6,%7},{%8,%9},{%0,%1,%2,%3};"
                    : "+f"(oacc[2*dp+1][0]), "+f"(oacc[2*dp+1][1]),
                      "+f"(oacc[2*dp+1][2]), "+f"(oacc[2*dp+1][3])
                    : "r"(a0), "r"(a1), "r"(a2), "r"(a3),
                      "r"(bv[2]), "r"(bv[3]));
            }
        }
    }

    float inv0 = 1.f / l0, inv1 = 1.f / l1;
    size_t row0 = ((size_t)(b*S_ + qt*64 + r0l)) * D_ + hoff;
    size_t row1 = ((size_t)(b*S_ + qt*64 + r1l)) * D_ + hoff;
#pragma unroll
    for (int j = 0; j < 8; j++) {
        int c = j*8 + tig*2;
        __half2 o0 = __floats2half2_rn(oacc[j][0]*inv0, oacc[j][1]*inv0);
        __half2 o1 = __floats2half2_rn(oacc[j][2]*inv1, oacc[j][3]*inv1);
        *(__half2*)(O + row0 + c) = o0;
        *(__half2*)(O + row1 + c) = o1;
    }
}

// ---------------- LayerNorm over D (f32 in, f16 out) ------------------------
__global__ void ln_kernel(const float* __restrict__ H,
                          const float* __restrict__ g,
                          const float* __restrict__ bb,
                          __half* __restrict__ out)
{
    int row = blockIdx.x;
    const float* h = H + (size_t)row * D_;
    __shared__ float red[256];
    int tid = threadIdx.x;

    float s = 0.f;
    for (int i = tid; i < D_; i += 256) s += h[i];
    red[tid] = s; __syncthreads();
    for (int o = 128; o; o >>= 1) { if (tid < o) red[tid] += red[tid+o]; __syncthreads(); }
    float mu = red[0] / (float)D_;
    __syncthreads();

    float v = 0.f;
    for (int i = tid; i < D_; i += 256) { float d = h[i] - mu; v += d*d; }
    red[tid] = v; __syncthreads();
    for (int o = 128; o; o >>= 1) { if (tid < o) red[tid] += red[tid+o]; __syncthreads(); }
    float rstd = rsqrtf(red[0] / (float)D_ + 1e-5f);

    __half* o2 = out + (size_t)row * D_;
    for (int i = tid; i < D_; i += 256)
        o2[i] = __float2half((h[i] - mu) * rstd * g[i] + bb[i]);
}

// ---------------- loss from per-block partials -------------------------------
__global__ void loss_partials_kernel(const float* __restrict__ logits,
                                     const int* __restrict__ targets,
                                     const float* __restrict__ pmax,
                                     const float* __restrict__ psum,
                                     float* __restrict__ rowloss)
{
    int row = blockIdx.x;
    int tid = threadIdx.x;
    __shared__ float rm[128], rs[128];

    float m = NEG_, s = 0.f;
    for (int j = tid; j < NBLK_; j += 128) {
        float m2 = pmax[(size_t)row * NBLK_ + j];
        float s2 = psum[(size_t)row * NBLK_ + j];
        float mm = fmaxf(m, m2);
        s = s * __expf(m - mm) + s2 * __expf(m2 - mm);
        m = mm;
    }
    rm[tid] = m; rs[tid] = s; __syncthreads();
    for (int o = 64; o; o >>= 1) {
        if (tid < o) {
            float m1 = rm[tid], s1 = rs[tid];
            float m2 = rm[tid+o], s2 = rs[tid+o];
            float mm = fmaxf(m1, m2);
            rm[tid] = mm;
            rs[tid] = s1 * __expf(m1 - mm) + s2 * __expf(m2 - mm);
        }
        __syncthreads();
    }
    if (tid == 0)
        rowloss[row] = -(logits[(size_t)row * V_ + targets[row]] - rm[0] - logf(rs[0]));
}

__global__ void loss_reduce_kernel(const float* __restrict__ rowloss,
                                   float* __restrict__ out)
{
    __shared__ float red[256];
    int tid = threadIdx.x;
    float s = 0.f;
    for (int i = tid; i < T_; i += 256) s += rowloss[i];
    red[tid] = s; __syncthreads();
    for (int o = 128; o; o >>= 1) { if (tid < o) red[tid] += red[tid+o]; __syncthreads(); }
    if (tid == 0) out[0] = red[0] / (float)T_;
}

// ---------------- launcher ---------------------------------------------------
extern "C" void kernel_launch(void* const* d_in, const int* in_sizes, int n_in,
                              void* d_out, int out_size)
{
    const int*   inputs  = (const int*)  d_in[0];
    const int*   targets = (const int*)  d_in[1];
    const float* wte     = (const float*)d_in[2];
    const float* wq      = (const float*)d_in[3];
    const float* bq      = (const float*)d_in[4];
    const float* wk      = (const float*)d_in[5];
    const float* bk      = (const float*)d_in[6];
    const float* wv      = (const float*)d_in[7];
    const float* bv      = (const float*)d_in[8];
    const float* wo      = (const float*)d_in[9];
    const float* bo      = (const float*)d_in[10];
    const float* w1      = (const float*)d_in[11];
    const float* b1      = (const float*)d_in[12];
    const float* w2      = (const float*)d_in[13];
    const float* b2      = (const float*)d_in[14];
    const float* ln_g    = (const float*)d_in[15];
    const float* ln_b    = (const float*)d_in[16];
    const float* w_out   = (const float*)d_in[17];
    const float* b_out   = (const float*)d_in[18];
    float* out = (float*)d_out;

    __half *x,*q,*k,*v,*ctx,*ao,*h1,*hn,*w;
    float *h2,*rowloss,*pmax,*psum,*bqkv;
    cudaGetSymbolAddress((void**)&x,   g_x);
    cudaGetSymbolAddress((void**)&q,   g_q);
    cudaGetSymbolAddress((void**)&k,   g_k);
    cudaGetSymbolAddress((void**)&v,   g_v);
    cudaGetSymbolAddress((void**)&ctx, g_ctx);
    cudaGetSymbolAddress((void**)&ao,  g_ao);
    cudaGetSymbolAddress((void**)&h1,  g_h1);
    cudaGetSymbolAddress((void**)&h2,  g_h2);
    cudaGetSymbolAddress((void**)&hn,  g_hn);
    cudaGetSymbolAddress((void**)&rowloss, g_rowloss);
    cudaGetSymbolAddress((void**)&pmax, g_pmax);
    cudaGetSymbolAddress((void**)&psum, g_psum);
    cudaGetSymbolAddress((void**)&bqkv, g_bqkv);
    cudaGetSymbolAddress((void**)&w,   g_w);

    const int SMEM_GEMM  = 3 * STGB;
    const int SMEM_GEMM6 = 3 * STG6B;   // 87552
    cudaFuncSetAttribute(hgemm_kernel, cudaFuncAttributeMaxDynamicSharedMemorySize, SMEM_GEMM);
    cudaFuncSetAttribute(hgemm256_kernel, cudaFuncAttributeMaxDynamicSharedMemorySize, SMEM_GEMM6);

    // 0. fused weight conversion (single launch)
    convert_all_kernel<<<(int)((CN5 + 255) / 256), 256>>>(
        wq, wk, wv, wo, w1, w2, w_out, bq, bk, bv, w, bqkv);

    // 1. embedding + positional encoding (fp16)
    embed_kernel<<<(T_*D_)/256, 256>>>(inputs, wte, x);

    // 2. fused Q,K,V projection (one GEMM, split epilogue)
    hgemm_kernel<<<dim3(T_/128, 3*D_/128), 256, SMEM_GEMM>>>(
        x, w+OFF_WQKV, bqkv, 0, q, k, v, T_, 3*D_, D_, 3*D_, 0, 2);

    // 3. causal multi-head attention (heavy tiles first)
    attn_tc_kernel<<<dim3(S_/64, B_*NH_), 128>>>(q, k, v, ctx);

    // 4. output projection -> fp16 ao
    dim3 gDD(T_/128, D_/128);
    hgemm_kernel<<<gDD, 256, SMEM_GEMM>>>(
        ctx, w+OFF_WO, bo, ao, 0,0,0, T_, D_, D_, D_, 0, 1);

    // 5. FFN (h1 fp16 + relu; h2 fp32 for LN)
    hgemm_kernel<<<dim3(T_/128, HID_/128), 256, SMEM_GEMM>>>(
        ao, w+OFF_W1, b1, h1, 0,0,0, T_, HID_, D_, HID_, 1, 1);
    hgemm_kernel<<<gDD, 256, SMEM_GEMM>>>(
        h1, w+OFF_W2, b2, h2, 0,0,0, T_, D_, HID_, D_, 0, 0);

    // 6. LayerNorm (fp32 in -> fp16 hn)
    ln_kernel<<<T_, 256>>>(h2, ln_g, ln_b, hn);

    // 7. vocab projection (BM=256) -> fp32 logits + fused softmax partials
    hgemm256_kernel<<<dim3(T_/256, NBLK_), 256, SMEM_GEMM6>>>(
        hn, w+OFF_WOUT, b_out, out, pmax, psum, NBLK_, T_, V_, D_, VP2_);

    // 8. cross-entropy loss from partials
    loss_partials_kernel<<<T_, 128>>>(out, targets, pmax, psum, rowloss);
    if (out_size > T_ * V_)
        loss_reduce_kernel<<<1, 256>>>(rowloss, out + (size_t)T_ * V_);
}

// round 15
// speedup vs baseline: 1.2238x; 1.2214x over previous
#include <cuda_runtime.h>
#include <cuda_fp16.h>
#include <math.h>

#define V_   50257
#define VP2_ 50304            // V padded to multiple of 128 (half scratch row stride)
#define NBLK_ 393             // vocab n-tiles of 128
#define D_   768
#define S_   2048
#define B_   2
#define HID_ 2048
#define NH_  12
#define HD_  64
#define T_   (B_*S_)   // 4096 tokens
#define NEG_ -1e30f

// ---------------- scratch (device globals; no allocation allowed) ----------
__device__ __half g_x  [T_*D_];
__device__ __half g_q  [T_*D_];
__device__ __half g_k  [T_*D_];
__device__ __half g_v  [T_*D_];
__device__ __half g_ctx[T_*D_];
__device__ __half g_ao [T_*D_];
__device__ __half g_h1 [T_*HID_];
__device__ float  g_h2 [T_*D_];
__device__ __half g_hn [T_*D_];
__device__ float  g_rowloss[T_];
__device__ float  g_pmax[T_*NBLK_];
__device__ float  g_psum[T_*NBLK_];
__device__ float  g_bqkv[3*D_];
// fp16 weight scratch: wqkv | wo | w1 | w2 | w_out(padded)  — CONTIGUOUS regions
#define OFF_WQKV 0
#define OFF_WO   (OFF_WQKV + D_*3*D_)
#define OFF_W1   (OFF_WO + D_*D_)
#define OFF_W2   (OFF_W1 + D_*HID_)
#define OFF_WOUT (OFF_W2 + HID_*D_)
#define W_TOTAL  (OFF_WOUT + D_*VP2_ + 64)
__device__ __half g_w[W_TOTAL];

// ---------------- fused weight conversion (ONE launch) -----------------------
#define CN0 221184L
#define CN1 (CN0 + 73728L)
#define CN2 (CN1 + 196608L)
#define CN3 (CN2 + 196608L)
#define CN4 (CN3 + 4829184L)
#define CN5 (CN4 + 288L)

__device__ __forceinline__ void cvt8(const float* __restrict__ src, __half* dst) {
    float4 a = *(const float4*)src;
    float4 b = *(const float4*)(src + 4);
    __half h[8] = { __float2half(a.x), __float2half(a.y), __float2half(a.z), __float2half(a.w),
                    __float2half(b.x), __float2half(b.y), __float2half(b.z), __float2half(b.w) };
    *(uint4*)dst = *(const uint4*)h;
}

__global__ void convert_all_kernel(const float* __restrict__ wq, const float* __restrict__ wk,
                                   const float* __restrict__ wv, const float* __restrict__ wo,
                                   const float* __restrict__ w1, const float* __restrict__ w2,
                                   const float* __restrict__ wout,
                                   const float* __restrict__ bq, const float* __restrict__ bk,
                                   const float* __restrict__ bv,
                                   __half* __restrict__ w, float* __restrict__ bqkv)
{
    long j = (long)blockIdx.x * blockDim.x + threadIdx.x;
    if (j >= CN5) return;
    if (j < CN0) {
        long off = j * 8;
        int r = (int)(off / (3*D_)), rem = (int)(off % (3*D_));
        int sel = rem / D_, c = rem % D_;
        const float* src = (sel == 0 ? wq : sel == 1 ? wk : wv) + (size_t)r * D_ + c;
        cvt8(src, w + off);
    } else if (j < CN1) {
        cvt8(wo + (j - CN0) * 8, w + j * 8);
    } else if (j < CN2) {
        cvt8(w1 + (j - CN1) * 8, w + j * 8);
    } else if (j < CN3) {
        cvt8(w2 + (j - CN2) * 8, w + j * 8);
    } else if (j < CN4) {
        long jj = j - CN3;
        int r = (int)(jj / (VP2_/8));
        int c = (int)(jj % (VP2_/8)) * 8;
        const float* src = wout + (size_t)r * V_ + c;
        __half tmp[8];
#pragma unroll
        for (int e = 0; e < 8; e++)
            tmp[e] = (c + e < V_) ? __float2half(__ldg(src + e)) : __half(0.f);
        *(uint4*)(w + j * 8) = *(const uint4*)tmp;
    } else {
        int i = (int)(j - CN4) * 8;
#pragma unroll
        for (int e = 0; e < 8; e++) {
            int idx = i + e;
            int sel = idx / D_, c = idx - sel * D_;
            bqkv[idx] = (sel == 0 ? bq : sel == 1 ? bk : bv)[c];
        }
    }
}

// ---------------- embedding + sinusoidal positional encoding ---------------
__global__ void embed_kernel(const int* __restrict__ inputs,
                             const float* __restrict__ wte,
                             __half* __restrict__ x)
{
    int idx = blockIdx.x * blockDim.x + threadIdx.x;
    if (idx >= T_*D_) return;
    int t = idx / D_;
    int d = idx - t * D_;
    int s = t & (S_-1);
    int tok = inputs[t];
    int i2 = (d >> 1) * 2;
    float div = expf((float)(-i2) * (logf(10000.0f) / (float)D_));
    float ang = (float)s * div;
    float pe = (d & 1) ? cosf(ang) : sinf(ang);
    x[idx] = __float2half(wte[(size_t)tok * D_ + d] + pe);
}

// ---------------- fp16 tensor-core GEMM, 3-stage cp.async, BK=32 -------------
// modes: 0 = f32 out, 1 = f16 out, 2 = qkv split f16 out, 3 = f32 out + loss partials
#define AST2 40
#define BST2 136
#define ASTB (128*AST2*2)
#define STGB (ASTB + 32*BST2*2)

__global__ __launch_bounds__(256, 2)
void hgemm_kernel(const __half* __restrict__ A, const __half* __restrict__ W,
                  const float* __restrict__ bias, void* __restrict__ Cout,
                  __half* __restrict__ dq, __half* __restrict__ dk, __half* __restrict__ dv,
                  float* __restrict__ pmax, float* __restrict__ psum, int nblk,
                  int M, int N, int K, int ldW, int relu, int mode)
{
    extern __shared__ char smc[];
    const int tid  = threadIdx.x;
    const int warp = tid >> 5;
    const int lane = tid & 31;
    const int gid  = lane >> 2;
    const int tig  = lane & 3;
    const int wm   = warp >> 2;
    const int wn   = warp & 3;
    const int m0 = blockIdx.x * 128;
    const int n0 = blockIdx.y * 128;
    const unsigned smem0 = (unsigned)__cvta_generic_to_shared(smc);

    float acc[4][4][4];
#pragma unroll
    for (int i = 0; i < 4; i++)
#pragma unroll
        for (int j = 0; j < 4; j++)
#pragma unroll
            for (int c = 0; c < 4; c++) acc[i][j][c] = 0.f;

    const int nk = K >> 5;

    auto load_stage = [&](int i) {
        unsigned sa = smem0 + (i % 3) * STGB;
        unsigned sb = sa + ASTB;
        const __half* Ab = A + (size_t)m0 * K + i * 32;
        const __half* Bb = W + (size_t)(i * 32) * ldW + n0;
#pragma unroll
        for (int t = 0; t < 2; t++) {
            int slot = t * 256 + tid;
            int r = slot >> 2, c = (slot & 3) * 8;
            asm volatile("cp.async.cg.shared.global [%0], [%1], 16;"
                         :: "r"(sa + (r * AST2 + c) * 2), "l"(Ab + (size_t)r * K + c));
        }
#pragma unroll
        for (int t = 0; t < 2; t++) {
            int slot = t * 256 + tid;
            int r = slot >> 4, c = (slot & 15) * 8;
            asm volatile("cp.async.cg.shared.global [%0], [%1], 16;"
                         :: "r"(sb + (r * BST2 + c) * 2), "l"(Bb + (size_t)r * ldW + c));
        }
        asm volatile("cp.async.commit_group;");
    };

    load_stage(0);
    load_stage(1);
    asm volatile("cp.async.wait_group 1;");
    __syncthreads();

    const int arow = lane & 15;
    const int acol = (lane >> 4) * 8;

    for (int i = 0; i < nk; i++) {
        unsigned sa = smem0 + (i % 3) * STGB;
        unsigned sb = sa + ASTB;

        if (i + 2 < nk) load_stage(i + 2);
        else            asm volatile("cp.async.commit_group;");

#pragma unroll
        for (int kk = 0; kk < 32; kk += 16) {
            unsigned af[4][4], bf[4][2];
#pragma unroll
            for (int mi = 0; mi < 4; mi++) {
                unsigned ad = sa + ((wm * 64 + mi * 16 + arow) * AST2 + kk + acol) * 2;
                asm volatile("ldmatrix.sync.aligned.m8n8.x4.shared.b16 {%0,%1,%2,%3}, [%4];"
                             : "=r"(af[mi][0]), "=r"(af[mi][1]),
                               "=r"(af[mi][2]), "=r"(af[mi][3]) : "r"(ad));
            }
#pragma unroll
            for (int nh = 0; nh < 2; nh++) {
                unsigned bd = sb + ((kk + arow) * BST2 + wn * 32 + nh * 16 + acol) * 2;
                asm volatile("ldmatrix.sync.aligned.m8n8.x4.trans.shared.b16 {%0,%1,%2,%3}, [%4];"
                             : "=r"(bf[2*nh][0]), "=r"(bf[2*nh][1]),
                               "=r"(bf[2*nh+1][0]), "=r"(bf[2*nh+1][1]) : "r"(bd));
            }
#pragma unroll
            for (int mi = 0; mi < 4; mi++)
#pragma unroll
                for (int ni = 0; ni < 4; ni++) {
                    asm volatile(
                        "mma.sync.aligned.m16n8k16.row.col.f32.f16.f16.f32 "
                        "{%0,%1,%2,%3},{%4,%5,%6,%7},{%8,%9},{%0,%1,%2,%3};"
                        : "+f"(acc[mi][ni][0]), "+f"(acc[mi][ni][1]),
                          "+f"(acc[mi][ni][2]), "+f"(acc[mi][ni][3])
                        : "r"(af[mi][0]), "r"(af[mi][1]),
                          "r"(af[mi][2]), "r"(af[mi][3]),
                          "r"(bf[ni][0]), "r"(bf[ni][1]));
                }
        }

        asm volatile("cp.async.wait_group 1;");
        __syncthreads();
    }

    // qkv destination select (each 128-col tile lies inside one segment)
    __half* qdst = 0; int qcol0 = 0;
    if (mode == 2) {
        int sel = n0 / D_;
        qdst  = (sel == 0 ? dq : sel == 1 ? dk : dv);
        qcol0 = n0 - sel * D_;
    }

    float* red = (float*)smc;   // [128][4][2] reuse after pipeline (4KB)

#pragma unroll
    for (int mi = 0; mi < 4; mi++) {
        int rl = wm * 64 + mi * 16 + gid;     // local row (half 0); +8 for half 1
        int r  = m0 + rl;
        float mA = NEG_, sA = 0.f, mB = NEG_, sB = 0.f;
#pragma unroll
        for (int ni = 0; ni < 4; ni++) {
            int cc = n0 + wn * 32 + ni * 8 + tig * 2;
            bool full = (cc + 1 < N);
            bool any  = (cc < N);
            float b0 = any  ? bias[cc]     : 0.f;
            float b1 = full ? bias[cc + 1] : 0.f;
            float v0 = acc[mi][ni][0] + b0;
            float v1 = acc[mi][ni][1] + b1;
            float v2 = acc[mi][ni][2] + b0;
            float v3 = acc[mi][ni][3] + b1;
            if (relu) {
                v0 = fmaxf(v0, 0.f); v1 = fmaxf(v1, 0.f);
                v2 = fmaxf(v2, 0.f); v3 = fmaxf(v3, 0.f);
            }
            if (mode == 1) {
                if (full) {
                    __half2 h0 = __floats2half2_rn(v0, v1);
                    __half2 h1 = __floats2half2_rn(v2, v3);
                    *(__half2*)((__half*)Cout + (size_t)r * N + cc)       = h0;
                    *(__half2*)((__half*)Cout + (size_t)(r + 8) * N + cc) = h1;
                } else if (any) {
                    ((__half*)Cout)[(size_t)r * N + cc]       = __float2half(v0);
                    ((__half*)Cout)[(size_t)(r + 8) * N + cc] = __float2half(v2);
                }
            } else if (mode == 2) {
                int lc = qcol0 + (cc - n0);
                if (full) {
                    __half2 h0 = __floats2half2_rn(v0, v1);
                    __half2 h1 = __floats2half2_rn(v2, v3);
                    *(__half2*)(qdst + (size_t)r * D_ + lc)       = h0;
                    *(__half2*)(qdst + (size_t)(r + 8) * D_ + lc) = h1;
                } else if (any) {
                    qdst[(size_t)r * D_ + lc]       = __float2half(v0);
                    qdst[(size_t)(r + 8) * D_ + lc] = __float2half(v2);
                }
            } else {
                float* C = (float*)Cout;
                if (any) {
                    asm volatile("st.global.cs.f32 [%0], %1;" :: "l"(C + (size_t)r * N + cc), "f"(v0));
                    asm volatile("st.global.cs.f32 [%0], %1;" :: "l"(C + (size_t)(r + 8) * N + cc), "f"(v2));
                    if (mode == 3) {
                        if (v0 > mA) { sA = sA * __expf(mA - v0) + 1.f; mA = v0; }
                        else         { sA += __expf(v0 - mA); }
                        if (v2 > mB) { sB = sB * __expf(mB - v2) + 1.f; mB = v2; }
                        else         { sB += __expf(v2 - mB); }
                    }
                }
                if (full) {
                    asm volatile("st.global.cs.f32 [%0], %1;" :: "l"(C + (size_t)r * N + cc + 1), "f"(v1));
                    asm volatile("st.global.cs.f32 [%0], %1;" :: "l"(C + (size_t)(r + 8) * N + cc + 1), "f"(v3));
                    if (mode == 3) {
                        if (v1 > mA) { sA = sA * __expf(mA - v1) + 1.f; mA = v1; }
                        else         { sA += __expf(v1 - mA); }
                        if (v3 > mB) { sB = sB * __expf(mB - v3) + 1.f; mB = v3; }
                        else         { sB += __expf(v3 - mB); }
                    }
                }
            }
        }
        if (mode == 3) {
#pragma unroll
            for (int o = 1; o <= 2; o <<= 1) {
                float m2 = __shfl_xor_sync(0xffffffffu, mA, o);
                float s2 = __shfl_xor_sync(0xffffffffu, sA, o);
                float mm = fmaxf(mA, m2);
                sA = sA * __expf(mA - mm) + s2 * __expf(m2 - mm);
                mA = mm;
                m2 = __shfl_xor_sync(0xffffffffu, mB, o);
                s2 = __shfl_xor_sync(0xffffffffu, sB, o);
                mm = fmaxf(mB, m2);
                sB = sB * __expf(mB - mm) + s2 * __expf(m2 - mm);
                mB = mm;
            }
            if (tig == 0) {
                red[((rl    ) * 4 + wn) * 2 + 0] = mA;
                red[((rl    ) * 4 + wn) * 2 + 1] = sA;
                red[((rl + 8) * 4 + wn) * 2 + 0] = mB;
                red[((rl + 8) * 4 + wn) * 2 + 1] = sB;
            }
        }
    }

    if (mode == 3) {
        __syncthreads();
        if (tid < 128) {
            float m = NEG_, s = 0.f;
#pragma unroll
            for (int wnn = 0; wnn < 4; wnn++) {
                float m2 = red[(tid * 4 + wnn) * 2 + 0];
                float s2 = red[(tid * 4 + wnn) * 2 + 1];
                float mm = fmaxf(m, m2);
                s = s * __expf(m - mm) + s2 * __expf(m2 - mm);
                m = mm;
            }
            pmax[(size_t)(m0 + tid) * nblk + blockIdx.y] = m;
            psum[(size_t)(m0 + tid) * nblk + blockIdx.y] = s;
        }
    }
}

// ---------------- tensor-core flash attention (FA2 layout) -------------------
#define ATS 72

__global__ __launch_bounds__(128)
void attn_tc_kernel(const __half* __restrict__ Q, const __half* __restrict__ K,
                    const __half* __restrict__ V, __half* __restrict__ O)
{
    __shared__ __half Qs[64*ATS];
    __shared__ __half Ks[64*ATS];
    __shared__ __half Vs[64*ATS];

    const int qt = (int)gridDim.x - 1 - (int)blockIdx.x;   // heavy tiles first
    const int bh = blockIdx.y;
    const int b  = bh / NH_;
    const int h  = bh - b * NH_;

    const int tid  = threadIdx.x;
    const int w    = tid >> 5;
    const int lane = tid & 31;
    const int gid  = lane >> 2;
    const int tig  = lane & 3;

    const size_t hoff = (size_t)h * HD_;
    const __half* Qg = Q + ((size_t)(b*S_ + qt*64)) * D_ + hoff;

    const __half2 sc2 = __floats2half2_rn(0.125f, 0.125f);
    for (int i = tid; i < 512; i += 128) {
        int r = i >> 3, c = (i & 7) * 8;
        uint4 u = *(const uint4*)(Qg + (size_t)r * D_ + c);
        __half2* hp = (__half2*)&u;
#pragma unroll
        for (int t = 0; t < 4; t++) hp[t] = __hmul2(hp[t], sc2);
        *(uint4*)&Qs[r*ATS + c] = u;
    }
    __syncthreads();

    const unsigned qb = (unsigned)__cvta_generic_to_shared(Qs);
    const unsigned kb = (unsigned)__cvta_generic_to_shared(Ks);
    const unsigned vb = (unsigned)__cvta_generic_to_shared(Vs);
    const int lrow = lane & 15;
    const int lcb  = (lane >> 4) * 8;

    unsigned aQ[4][4];
#pragma unroll
    for (int t = 0; t < 4; t++) {
        unsigned ad = qb + (unsigned)(((w*16 + lrow) * ATS + t*16 + lcb) * 2);
        asm volatile("ldmatrix.sync.aligned.m8n8.x4.shared.b16 {%0,%1,%2,%3}, [%4];"
                     : "=r"(aQ[t][0]), "=r"(aQ[t][1]), "=r"(aQ[t][2]), "=r"(aQ[t][3])
                     : "r"(ad));
    }

    float oacc[8][4];
#pragma unroll
    for (int j = 0; j < 8; j++)
#pragma unroll
        for (int c = 0; c < 4; c++) oacc[j][c] = 0.f;
    float m0 = -INFINITY, m1 = -INFINITY, l0 = 0.f, l1 = 0.f;

    const int r0l = w*16 + gid;
    const int r1l = r0l + 8;

    for (int kt = 0; kt <= qt; kt++) {
        __syncthreads();
        const __half* Kg = K + ((size_t)(b*S_ + kt*64)) * D_ + hoff;
        const __half* Vg = V + ((size_t)(b*S_ + kt*64)) * D_ + hoff;
        for (int i = tid; i < 1024; i += 128) {
            int r = (i >> 3) & 63, c = (i & 7) * 8;
            if (i < 512)
                *(uint4*)&Ks[r*ATS + c] = *(const uint4*)(Kg + (size_t)r * D_ + c);
            else
                *(uint4*)&Vs[r*ATS + c] = *(const uint4*)(Vg + (size_t)r * D_ + c);
        }
        __syncthreads();

        float sacc[8][4];
#pragma unroll
        for (int j = 0; j < 8; j++)
#pragma unroll
            for (int c = 0; c < 4; c++) sacc[j][c] = 0.f;

#pragma unroll
        for (int t = 0; t < 4; t++) {
#pragma unroll
            for (int jp = 0; jp < 4; jp++) {
                unsigned bk[4];
                unsigned ad = kb + (unsigned)(((jp*16 + lrow) * ATS + t*16 + lcb) * 2);
                asm volatile("ldmatrix.sync.aligned.m8n8.x4.shared.b16 {%0,%1,%2,%3}, [%4];"
                             : "=r"(bk[0]), "=r"(bk[1]), "=r"(bk[2]), "=r"(bk[3])
                             : "r"(ad));
                asm volatile(
                    "mma.sync.aligned.m16n8k16.row.col.f32.f16.f16.f32 "
                    "{%0,%1,%2,%3},{%4,%5,%6,%7},{%8,%9},{%0,%1,%2,%3};"
                    : "+f"(sacc[2*jp][0]), "+f"(sacc[2*jp][1]),
                      "+f"(sacc[2*jp][2]), "+f"(sacc[2*jp][3])
                    : "r"(aQ[t][0]), "r"(aQ[t][1]), "r"(aQ[t][2]), "r"(aQ[t][3]),
                      "r"(bk[0]), "r"(bk[2]));
                asm volatile(
                    "mma.sync.aligned.m16n8k16.row.col.f32.f16.f16.f32 "
                    "{%0,%1,%2,%3},{%4,%5,%6,%7},{%8,%9},{%0,%1,%2,%3};"
                    : "+f"(sacc[2*jp+1][0]), "+f"(sacc[2*jp+1][1]),
                      "+f"(sacc[2*jp+1][2]), "+f"(sacc[2*jp+1][3])
                    : "r"(aQ[t][0]), "r"(aQ[t][1]), "r"(aQ[t][2]), "r"(aQ[t][3]),
                      "r"(bk[1]), "r"(bk[3]));
            }
        }

        if (kt == qt) {
#pragma unroll
            for (int j = 0; j < 8; j++) {
                int c0 = j*8 + tig*2;
                if (c0     > r0l) sacc[j][0] = -INFINITY;
                if (c0 + 1 > r0l) sacc[j][1] = -INFINITY;
                if (c0     > r1l) sacc[j][2] = -INFINITY;
                if (c0 + 1 > r1l) sacc[j][3] = -INFINITY;
            }
        }

        float mx0 = -INFINITY, mx1 = -INFINITY;
#pragma unroll
        for (int j = 0; j < 8; j++) {
            mx0 = fmaxf(mx0, fmaxf(sacc[j][0], sacc[j][1]));
            mx1 = fmaxf(mx1, fmaxf(sacc[j][2], sacc[j][3]));
        }
#pragma unroll
        for (int o = 1; o <= 2; o <<= 1) {
            mx0 = fmaxf(mx0, __shfl_xor_sync(0xffffffffu, mx0, o));
            mx1 = fmaxf(mx1, __shfl_xor_sync(0xffffffffu, mx1, o));
        }
        float nm0 = fmaxf(m0, mx0), nm1 = fmaxf(m1, mx1);
        float corr0 = __expf(m0 - nm0), corr1 = __expf(m1 - nm1);

        unsigned pa0[8], pa1[8];
        float sum0 = 0.f, sum1 = 0.f;
#pragma unroll
        for (int j = 0; j < 8; j++) {
            float p00 = __expf(sacc[j][0] - nm0);
            float p01 = __expf(sacc[j][1] - nm0);
            float p10 = __expf(sacc[j][2] - nm1);
            float p11 = __expf(sacc[j][3] - nm1);
            sum0 += p00 + p01;
            sum1 += p10 + p11;
            __half2 h0 = __floats2half2_rn(p00, p01);
            __half2 h1 = __floats2half2_rn(p10, p11);
            pa0[j] = *(unsigned*)&h0;
            pa1[j] = *(unsigned*)&h1;
        }
#pragma unroll
        for (int o = 1; o <= 2; o <<= 1) {
            sum0 += __shfl_xor_sync(0xffffffffu, sum0, o);
            sum1 += __shfl_xor_sync(0xffffffffu, sum1, o);
        }
        l0 = l0 * corr0 + sum0;
        l1 = l1 * corr1 + sum1;
        m0 = nm0; m1 = nm1;
#pragma unroll
        for (int j = 0; j < 8; j++) {
            oacc[j][0] *= corr0; oacc[j][1] *= corr0;
            oacc[j][2] *= corr1; oacc[j][3] *= corr1;
        }

#pragma unroll
        for (int kc = 0; kc < 4; kc++) {
            unsigned a0 = pa0[2*kc], a1 = pa1[2*kc], a2 = pa0[2*kc+1], a3 = pa1[2*kc+1];
#pragma unroll
            for (int dp = 0; dp < 4; dp++) {
                unsigned bv[4];
                unsigned ad = vb + (unsigned)(((kc*16 + lrow) * ATS + dp*16 + lcb) * 2);
                asm volatile("ldmatrix.sync.aligned.m8n8.x4.trans.shared.b16 {%0,%1,%2,%3}, [%4];"
                             : "=r"(bv[0]), "=r"(bv[1]), "=r"(bv[2]), "=r"(bv[3])
                             : "r"(ad));
                asm volatile(
                    "mma.sync.aligned.m16n8k16.row.col.f32.f16.f16.f32 "
                    "{%0,%1,%2,%3},{%4,%5,%6,%7},{%8,%9},{%0,%1,%2,%3};"
                    : "+f"(oacc[2*dp][0]), "+f"(oacc[2*dp][1]),
                      "+f"(oacc[2*dp][2]), "+f"(oacc[2*dp][3])
                    : "r"(a0), "r"(a1), "r"(a2), "r"(a3),
                      "r"(bv[0]), "r"(bv[1]));
                asm volatile(
                    "mma.sync.aligned.m16n8k16.row.col.f32.f16.f16.f32 "
                    "{%0,%1,%2,%3},{%4,%5,%6,%7},{%8,%9},{%0,%1,%2,%3};"
                    : "+f"(oacc[2*dp+1][0]), "+f"(oacc[2*dp+1][1]),
                      "+f"(oacc[2*dp+1][2]), "+f"(oacc[2*dp+1][3])
                    : "r"(a0), "r"(a1), "r"(a2), "r"(a3),
                      "r"(bv[2]), "r"(bv[3]));
            }
        }
    }

    float inv0 = 1.f / l0, inv1 = 1.f / l1;
    size_t row0 = ((size_t)(b*S_ + qt*64 + r0l)) * D_ + hoff;
    size_t row1 = ((size_t)(b*S_ + qt*64 + r1l)) * D_ + hoff;
#pragma unroll
    for (int j = 0; j < 8; j++) {
        int c = j*8 + tig*2;
        __half2 o0 = __floats2half2_rn(oacc[j][0]*inv0, oacc[j][1]*inv0);
        __half2 o1 = __floats2half2_rn(oacc[j][2]*inv1, oacc[j][3]*inv1);
        *(__half2*)(O + row0 + c) = o0;
        *(__half2*)(O + row1 + c) = o1;
    }
}

// ---------------- LayerNorm over D (f32 in, f16 out) ------------------------
__global__ void ln_kernel(const float* __restrict__ H,
                          const float* __restrict__ g,
                          const float* __restrict__ bb,
                          __half* __restrict__ out)
{
    int row = blockIdx.x;
    const float* h = H + (size_t)row * D_;
    __shared__ float red[256];
    int tid = threadIdx.x;

    float s = 0.f;
    for (int i = tid; i < D_; i += 256) s += h[i];
    red[tid] = s; __syncthreads();
    for (int o = 128; o; o >>= 1) { if (tid < o) red[tid] += red[tid+o]; __syncthreads(); }
    float mu = red[0] / (float)D_;
    __syncthreads();

    float v = 0.f;
    for (int i = tid; i < D_; i += 256) { float d = h[i] - mu; v += d*d; }
    red[tid] = v; __syncthreads();
    for (int o = 128; o; o >>= 1) { if (tid < o) red[tid] += red[tid+o]; __syncthreads(); }
    float rstd = rsqrtf(red[0] / (float)D_ + 1e-5f);

    __half* o2 = out + (size_t)row * D_;
    for (int i = tid; i < D_; i += 256)
        o2[i] = __float2half((h[i] - mu) * rstd * g[i] + bb[i]);
}

// ---------------- loss from per-block partials -------------------------------
__global__ void loss_partials_kernel(const float* __restrict__ logits,
                                     const int* __restrict__ targets,
                                     const float* __restrict__ pmax,
                                     const float* __restrict__ psum,
                                     float* __restrict__ rowloss)
{
    int row = blockIdx.x;
    int tid = threadIdx.x;
    __shared__ float rm[128], rs[128];

    float m = NEG_, s = 0.f;
    for (int j = tid; j < NBLK_; j += 128) {
        float m2 = pmax[(size_t)row * NBLK_ + j];
        float s2 = psum[(size_t)row * NBLK_ + j];
        float mm = fmaxf(m, m2);
        s = s * __expf(m - mm) + s2 * __expf(m2 - mm);
        m = mm;
    }
    rm[tid] = m; rs[tid] = s; __syncthreads();
    for (int o = 64; o; o >>= 1) {
        if (tid < o) {
            float m1 = rm[tid], s1 = rs[tid];
            float m2 = rm[tid+o], s2 = rs[tid+o];
            float mm = fmaxf(m1, m2);
            rm[tid] = mm;
            rs[tid] = s1 * __expf(m1 - mm) + s2 * __expf(m2 - mm);
        }
        __syncthreads();
    }
    if (tid == 0)
        rowloss[row] = -(logits[(size_t)row * V_ + targets[row]] - rm[0] - logf(rs[0]));
}

__global__ void loss_reduce_kernel(const float* __restrict__ rowloss,
                                   float* __restrict__ out)
{
    __shared__ float red[256];
    int tid = threadIdx.x;
    float s = 0.f;
    for (int i = tid; i < T_; i += 256) s += rowloss[i];
    red[tid] = s; __syncthreads();
    for (int o = 128; o; o >>= 1) { if (tid < o) red[tid] += red[tid+o]; __syncthreads(); }
    if (tid == 0) out[0] = red[0] / (float)T_;
}

// ---------------- launcher ---------------------------------------------------
extern "C" void kernel_launch(void* const* d_in, const int* in_sizes, int n_in,
                              void* d_out, int out_size)
{
    const int*   inputs  = (const int*)  d_in[0];
    const int*   targets = (const int*)  d_in[1];
    const float* wte     = (const float*)d_in[2];
    const float* wq      = (const float*)d_in[3];
    const float* bq      = (const float*)d_in[4];
    const float* wk      = (const float*)d_in[5];
    const float* bk      = (const float*)d_in[6];
    const float* wv      = (const float*)d_in[7];
    const float* bv      = (const float*)d_in[8];
    const float* wo      = (const float*)d_in[9];
    const float* bo      = (const float*)d_in[10];
    const float* w1      = (const float*)d_in[11];
    const float* b1      = (const float*)d_in[12];
    const float* w2      = (const float*)d_in[13];
    const float* b2      = (const float*)d_in[14];
    const float* ln_g    = (const float*)d_in[15];
    const float* ln_b    = (const float*)d_in[16];
    const float* w_out   = (const float*)d_in[17];
    const float* b_out   = (const float*)d_in[18];
    float* out = (float*)d_out;

    __half *x,*q,*k,*v,*ctx,*ao,*h1,*hn,*w;
    float *h2,*rowloss,*pmax,*psum,*bqkv;
    cudaGetSymbolAddress((void**)&x,   g_x);
    cudaGetSymbolAddress((void**)&q,   g_q);
    cudaGetSymbolAddress((void**)&k,   g_k);
    cudaGetSymbolAddress((void**)&v,   g_v);
    cudaGetSymbolAddress((void**)&ctx, g_ctx);
    cudaGetSymbolAddress((void**)&ao,  g_ao);
    cudaGetSymbolAddress((void**)&h1,  g_h1);
    cudaGetSymbolAddress((void**)&h2,  g_h2);
    cudaGetSymbolAddress((void**)&hn,  g_hn);
    cudaGetSymbolAddress((void**)&rowloss, g_rowloss);
    cudaGetSymbolAddress((void**)&pmax, g_pmax);
    cudaGetSymbolAddress((void**)&psum, g_psum);
    cudaGetSymbolAddress((void**)&bqkv, g_bqkv);
    cudaGetSymbolAddress((void**)&w,   g_w);

    const int SMEM_GEMM = 3 * STGB;
    cudaFuncSetAttribute(hgemm_kernel, cudaFuncAttributeMaxDynamicSharedMemorySize, SMEM_GEMM);

    // 0. fused weight conversion (single launch)
    convert_all_kernel<<<(int)((CN5 + 255) / 256), 256>>>(
        wq, wk, wv, wo, w1, w2, w_out, bq, bk, bv, w, bqkv);

    // 1. embedding + positional encoding (fp16)
    embed_kernel<<<(T_*D_)/256, 256>>>(inputs, wte, x);

    // 2. fused Q,K,V projection (one GEMM, split epilogue)
    hgemm_kernel<<<dim3(T_/128, 3*D_/128), 256, SMEM_GEMM>>>(
        x, w+OFF_WQKV, bqkv, 0, q, k, v, 0, 0, 0, T_, 3*D_, D_, 3*D_, 0, 2);

    // 3. causal multi-head attention (heavy tiles first)
    attn_tc_kernel<<<dim3(S_/64, B_*NH_), 128>>>(q, k, v, ctx);

    // 4. output projection -> fp16 ao
    dim3 gDD(T_/128, D_/128);
    hgemm_kernel<<<gDD, 256, SMEM_GEMM>>>(
        ctx, w+OFF_WO, bo, ao, 0,0,0, 0,0,0, T_, D_, D_, D_, 0, 1);

    // 5. FFN (h1 fp16 + relu; h2 fp32 for LN)
    hgemm_kernel<<<dim3(T_/128, HID_/128), 256, SMEM_GEMM>>>(
        ao, w+OFF_W1, b1, h1, 0,0,0, 0,0,0, T_, HID_, D_, HID_, 1, 1);
    hgemm_kernel<<<gDD, 256, SMEM_GEMM>>>(
        h1, w+OFF_W2, b2, h2, 0,0,0, 0,0,0, T_, D_, HID_, D_, 0, 0);

    // 6. LayerNorm (fp32 in -> fp16 hn)
    ln_kernel<<<T_, 256>>>(h2, ln_g, ln_b, hn);

    // 7. vocab projection (BM=128, 2 CTAs/SM) -> fp32 logits + loss partials
    hgemm_kernel<<<dim3(T_/128, NBLK_), 256, SMEM_GEMM>>>(
        hn, w+OFF_WOUT, b_out, out, 0,0,0, pmax, psum, NBLK_,
        T_, V_, D_, VP2_, 0, 3);

    // 8. cross-entropy loss from partials
    loss_partials_kernel<<<T_, 128>>>(out, targets, pmax, psum, rowloss);
    if (out_size > T_ * V_)
        loss_reduce_kernel<<<1, 256>>>(rowloss, out + (size_t)T_ * V_);
}

// round 16
// speedup vs baseline: 1.2260x; 1.0018x over previous
#include <cuda_runtime.h>
#include <cuda_fp16.h>
#include <math.h>

#define V_   50257
#define VP2_ 50304            // V padded to multiple of 128 (half scratch row stride)
#define NBLK_ 393             // vocab n-tiles of 128
#define D_   768
#define S_   2048
#define B_   2
#define HID_ 2048
#define NH_  12
#define HD_  64
#define T_   (B_*S_)   // 4096 tokens
#define NEG_ -1e30f

// ---------------- scratch (device globals; no allocation allowed) ----------
__device__ __half g_x  [T_*D_];
__device__ __half g_q  [T_*D_];
__device__ __half g_k  [T_*D_];
__device__ __half g_v  [T_*D_];
__device__ __half g_ctx[T_*D_];
__device__ __half g_ao [T_*D_];
__device__ __half g_h1 [T_*HID_];
__device__ float  g_h2 [T_*D_];
__device__ __half g_hn [T_*D_];
__device__ float  g_rowloss[T_];
__device__ float  g_pmax[T_*NBLK_];
__device__ float  g_psum[T_*NBLK_];
__device__ float  g_bqkv[3*D_];
// fp16 weight scratch: wqkv | wo | w1 | w2 | w_out(padded)  — CONTIGUOUS regions
#define OFF_WQKV 0
#define OFF_WO   (OFF_WQKV + D_*3*D_)
#define OFF_W1   (OFF_WO + D_*D_)
#define OFF_W2   (OFF_W1 + D_*HID_)
#define OFF_WOUT (OFF_W2 + HID_*D_)
#define W_TOTAL  (OFF_WOUT + D_*VP2_ + 64)
__device__ __half g_w[W_TOTAL];

// ---------------- fused weight conversion (ONE launch) -----------------------
#define CN0 221184L
#define CN1 (CN0 + 73728L)
#define CN2 (CN1 + 196608L)
#define CN3 (CN2 + 196608L)
#define CN4 (CN3 + 4829184L)
#define CN5 (CN4 + 288L)

__device__ __forceinline__ void cvt8(const float* __restrict__ src, __half* dst) {
    float4 a = *(const float4*)src;
    float4 b = *(const float4*)(src + 4);
    __half h[8] = { __float2half(a.x), __float2half(a.y), __float2half(a.z), __float2half(a.w),
                    __float2half(b.x), __float2half(b.y), __float2half(b.z), __float2half(b.w) };
    *(uint4*)dst = *(const uint4*)h;
}

__global__ void convert_all_kernel(const float* __restrict__ wq, const float* __restrict__ wk,
                                   const float* __restrict__ wv, const float* __restrict__ wo,
                                   const float* __restrict__ w1, const float* __restrict__ w2,
                                   const float* __restrict__ wout,
                                   const float* __restrict__ bq, const float* __restrict__ bk,
                                   const float* __restrict__ bv,
                                   __half* __restrict__ w, float* __restrict__ bqkv)
{
    long j = (long)blockIdx.x * blockDim.x + threadIdx.x;
    if (j >= CN5) return;
    if (j < CN0) {
        long off = j * 8;
        int r = (int)(off / (3*D_)), rem = (int)(off % (3*D_));
        int sel = rem / D_, c = rem % D_;
        const float* src = (sel == 0 ? wq : sel == 1 ? wk : wv) + (size_t)r * D_ + c;
        cvt8(src, w + off);
    } else if (j < CN1) {
        cvt8(wo + (j - CN0) * 8, w + j * 8);
    } else if (j < CN2) {
        cvt8(w1 + (j - CN1) * 8, w + j * 8);
    } else if (j < CN3) {
        cvt8(w2 + (j - CN2) * 8, w + j * 8);
    } else if (j < CN4) {
        long jj = j - CN3;
        int r = (int)(jj / (VP2_/8));
        int c = (int)(jj % (VP2_/8)) * 8;
        const float* src = wout + (size_t)r * V_ + c;
        __half tmp[8];
#pragma unroll
        for (int e = 0; e < 8; e++)
            tmp[e] = (c + e < V_) ? __float2half(__ldg(src + e)) : __half(0.f);
        *(uint4*)(w + j * 8) = *(const uint4*)tmp;
    } else {
        int i = (int)(j - CN4) * 8;
#pragma unroll
        for (int e = 0; e < 8; e++) {
            int idx = i + e;
            int sel = idx / D_, c = idx - sel * D_;
            bqkv[idx] = (sel == 0 ? bq : sel == 1 ? bk : bv)[c];
        }
    }
}

// ---------------- embedding + sinusoidal positional encoding ---------------
__global__ void embed_kernel(const int* __restrict__ inputs,
                             const float* __restrict__ wte,
                             __half* __restrict__ x)
{
    int idx = blockIdx.x * blockDim.x + threadIdx.x;
    if (idx >= T_*D_) return;
    int t = idx / D_;
    int d = idx - t * D_;
    int s = t & (S_-1);
    int tok = inputs[t];
    int i2 = (d >> 1) * 2;
    float div = expf((float)(-i2) * (logf(10000.0f) / (float)D_));
    float ang = (float)s * div;
    float pe = (d & 1) ? cosf(ang) : sinf(ang);
    x[idx] = __float2half(wte[(size_t)tok * D_ + d] + pe);
}

// ---------------- fp16 tensor-core GEMM, 3-stage cp.async, BK=32 -------------
// modes: 0 = f32 out, 1 = f16 out, 2 = qkv split f16 out, 3 = f32 out + loss partials
#define AST2 40
#define BST2 136
#define ASTB (128*AST2*2)
#define STGB (ASTB + 32*BST2*2)

__global__ __launch_bounds__(256, 2)
void hgemm_kernel(const __half* __restrict__ A, const __half* __restrict__ W,
                  const float* __restrict__ bias, void* __restrict__ Cout,
                  __half* __restrict__ dq, __half* __restrict__ dk, __half* __restrict__ dv,
                  float* __restrict__ pmax, float* __restrict__ psum, int nblk,
                  int M, int N, int K, int ldW, int relu, int mode)
{
    extern __shared__ char smc[];
    const int tid  = threadIdx.x;
    const int warp = tid >> 5;
    const int lane = tid & 31;
    const int gid  = lane >> 2;
    const int tig  = lane & 3;
    const int wm   = warp >> 2;
    const int wn   = warp & 3;
    const int m0 = blockIdx.x * 128;
    const int n0 = blockIdx.y * 128;
    const unsigned smem0 = (unsigned)__cvta_generic_to_shared(smc);

    float acc[4][4][4];
#pragma unroll
    for (int i = 0; i < 4; i++)
#pragma unroll
        for (int j = 0; j < 4; j++)
#pragma unroll
            for (int c = 0; c < 4; c++) acc[i][j][c] = 0.f;

    const int nk = K >> 5;

    auto load_stage = [&](int i) {
        unsigned sa = smem0 + (i % 3) * STGB;
        unsigned sb = sa + ASTB;
        const __half* Ab = A + (size_t)m0 * K + i * 32;
        const __half* Bb = W + (size_t)(i * 32) * ldW + n0;
#pragma unroll
        for (int t = 0; t < 2; t++) {
            int slot = t * 256 + tid;
            int r = slot >> 2, c = (slot & 3) * 8;
            asm volatile("cp.async.cg.shared.global [%0], [%1], 16;"
                         :: "r"(sa + (r * AST2 + c) * 2), "l"(Ab + (size_t)r * K + c));
        }
#pragma unroll
        for (int t = 0; t < 2; t++) {
            int slot = t * 256 + tid;
            int r = slot >> 4, c = (slot & 15) * 8;
            asm volatile("cp.async.cg.shared.global [%0], [%1], 16;"
                         :: "r"(sb + (r * BST2 + c) * 2), "l"(Bb + (size_t)r * ldW + c));
        }
        asm volatile("cp.async.commit_group;");
    };

    load_stage(0);
    load_stage(1);
    asm volatile("cp.async.wait_group 1;");
    __syncthreads();

    const int arow = lane & 15;
    const int acol = (lane >> 4) * 8;

    for (int i = 0; i < nk; i++) {
        unsigned sa = smem0 + (i % 3) * STGB;
        unsigned sb = sa + ASTB;

        if (i + 2 < nk) load_stage(i + 2);
        else            asm volatile("cp.async.commit_group;");

#pragma unroll
        for (int kk = 0; kk < 32; kk += 16) {
            unsigned af[4][4], bf[4][2];
#pragma unroll
            for (int mi = 0; mi < 4; mi++) {
                unsigned ad = sa + ((wm * 64 + mi * 16 + arow) * AST2 + kk + acol) * 2;
                asm volatile("ldmatrix.sync.aligned.m8n8.x4.shared.b16 {%0,%1,%2,%3}, [%4];"
                             : "=r"(af[mi][0]), "=r"(af[mi][1]),
                               "=r"(af[mi][2]), "=r"(af[mi][3]) : "r"(ad));
            }
#pragma unroll
            for (int nh = 0; nh < 2; nh++) {
                unsigned bd = sb + ((kk + arow) * BST2 + wn * 32 + nh * 16 + acol) * 2;
                asm volatile("ldmatrix.sync.aligned.m8n8.x4.trans.shared.b16 {%0,%1,%2,%3}, [%4];"
                             : "=r"(bf[2*nh][0]), "=r"(bf[2*nh][1]),
                               "=r"(bf[2*nh+1][0]), "=r"(bf[2*nh+1][1]) : "r"(bd));
            }
#pragma unroll
            for (int mi = 0; mi < 4; mi++)
#pragma unroll
                for (int ni = 0; ni < 4; ni++) {
                    asm volatile(
                        "mma.sync.aligned.m16n8k16.row.col.f32.f16.f16.f32 "
                        "{%0,%1,%2,%3},{%4,%5,%6,%7},{%8,%9},{%0,%1,%2,%3};"
                        : "+f"(acc[mi][ni][0]), "+f"(acc[mi][ni][1]),
                          "+f"(acc[mi][ni][2]), "+f"(acc[mi][ni][3])
                        : "r"(af[mi][0]), "r"(af[mi][1]),
                          "r"(af[mi][2]), "r"(af[mi][3]),
                          "r"(bf[ni][0]), "r"(bf[ni][1]));
                }
        }

        asm volatile("cp.async.wait_group 1;");
        __syncthreads();
    }

    // qkv destination select (each 128-col tile lies inside one segment)
    __half* qdst = 0; int qcol0 = 0;
    if (mode == 2) {
        int sel = n0 / D_;
        qdst  = (sel == 0 ? dq : sel == 1 ? dk : dv);
        qcol0 = n0 - sel * D_;
    }

    float* red = (float*)smc;   // [128][4][2] reuse after pipeline (4KB)

#pragma unroll
    for (int mi = 0; mi < 4; mi++) {
        int rl = wm * 64 + mi * 16 + gid;     // local row (half 0); +8 for half 1
        int r  = m0 + rl;
        float mA = NEG_, sA = 0.f, mB = NEG_, sB = 0.f;
#pragma unroll
        for (int ni = 0; ni < 4; ni++) {
            int cc = n0 + wn * 32 + ni * 8 + tig * 2;
            bool full = (cc + 1 < N);
            bool any  = (cc < N);
            float b0 = any  ? bias[cc]     : 0.f;
            float b1 = full ? bias[cc + 1] : 0.f;
            float v0 = acc[mi][ni][0] + b0;
            float v1 = acc[mi][ni][1] + b1;
            float v2 = acc[mi][ni][2] + b0;
            float v3 = acc[mi][ni][3] + b1;
            if (relu) {
                v0 = fmaxf(v0, 0.f); v1 = fmaxf(v1, 0.f);
                v2 = fmaxf(v2, 0.f); v3 = fmaxf(v3, 0.f);
            }
            if (mode == 1) {
                if (full) {
                    __half2 h0 = __floats2half2_rn(v0, v1);
                    __half2 h1 = __floats2half2_rn(v2, v3);
                    *(__half2*)((__half*)Cout + (size_t)r * N + cc)       = h0;
                    *(__half2*)((__half*)Cout + (size_t)(r + 8) * N + cc) = h1;
                } else if (any) {
                    ((__half*)Cout)[(size_t)r * N + cc]       = __float2half(v0);
                    ((__half*)Cout)[(size_t)(r + 8) * N + cc] = __float2half(v2);
                }
            } else if (mode == 2) {
                int lc = qcol0 + (cc - n0);
                if (full) {
                    __half2 h0 = __floats2half2_rn(v0, v1);
                    __half2 h1 = __floats2half2_rn(v2, v3);
                    *(__half2*)(qdst + (size_t)r * D_ + lc)       = h0;
                    *(__half2*)(qdst + (size_t)(r + 8) * D_ + lc) = h1;
                } else if (any) {
                    qdst[(size_t)r * D_ + lc]       = __float2half(v0);
                    qdst[(size_t)(r + 8) * D_ + lc] = __float2half(v2);
                }
            } else {
                float* C = (float*)Cout;
                if (any) {
                    asm volatile("st.global.cs.f32 [%0], %1;" :: "l"(C + (size_t)r * N + cc), "f"(v0));
                    asm volatile("st.global.cs.f32 [%0], %1;" :: "l"(C + (size_t)(r + 8) * N + cc), "f"(v2));
                    if (mode == 3) {
                        if (v0 > mA) { sA = sA * __expf(mA - v0) + 1.f; mA = v0; }
                        else         { sA += __expf(v0 - mA); }
                        if (v2 > mB) { sB = sB * __expf(mB - v2) + 1.f; mB = v2; }
                        else         { sB += __expf(v2 - mB); }
                    }
                }
                if (full) {
                    asm volatile("st.global.cs.f32 [%0], %1;" :: "l"(C + (size_t)r * N + cc + 1), "f"(v1));
                    asm volatile("st.global.cs.f32 [%0], %1;" :: "l"(C + (size_t)(r + 8) * N + cc + 1), "f"(v3));
                    if (mode == 3) {
                        if (v1 > mA) { sA = sA * __expf(mA - v1) + 1.f; mA = v1; }
                        else         { sA += __expf(v1 - mA); }
                        if (v3 > mB) { sB = sB * __expf(mB - v3) + 1.f; mB = v3; }
                        else         { sB += __expf(v3 - mB); }
                    }
                }
            }
        }
        if (mode == 3) {
#pragma unroll
            for (int o = 1; o <= 2; o <<= 1) {
                float m2 = __shfl_xor_sync(0xffffffffu, mA, o);
                float s2 = __shfl_xor_sync(0xffffffffu, sA, o);
                float mm = fmaxf(mA, m2);
                sA = sA * __expf(mA - mm) + s2 * __expf(m2 - mm);
                mA = mm;
                m2 = __shfl_xor_sync(0xffffffffu, mB, o);
                s2 = __shfl_xor_sync(0xffffffffu, sB, o);
                mm = fmaxf(mB, m2);
                sB = sB * __expf(mB - mm) + s2 * __expf(m2 - mm);
                mB = mm;
            }
            if (tig == 0) {
                red[((rl    ) * 4 + wn) * 2 + 0] = mA;
                red[((rl    ) * 4 + wn) * 2 + 1] = sA;
                red[((rl + 8) * 4 + wn) * 2 + 0] = mB;
                red[((rl + 8) * 4 + wn) * 2 + 1] = sB;
            }
        }
    }

    if (mode == 3) {
        __syncthreads();
        if (tid < 128) {
            float m = NEG_, s = 0.f;
#pragma unroll
            for (int wnn = 0; wnn < 4; wnn++) {
                float m2 = red[(tid * 4 + wnn) * 2 + 0];
                float s2 = red[(tid * 4 + wnn) * 2 + 1];
                float mm = fmaxf(m, m2);
                s = s * __expf(m - mm) + s2 * __expf(m2 - mm);
                m = mm;
            }
            pmax[(size_t)(m0 + tid) * nblk + blockIdx.y] = m;
            psum[(size_t)(m0 + tid) * nblk + blockIdx.y] = s;
        }
    }
}

// ---------------- tensor-core flash attention (FA2 layout) -------------------
#define ATS 72

__global__ __launch_bounds__(128)
void attn_tc_kernel(const __half* __restrict__ Q, const __half* __restrict__ K,
                    const __half* __restrict__ V, __half* __restrict__ O)
{
    __shared__ __half Qs[64*ATS];
    __shared__ __half Ks[64*ATS];
    __shared__ __half Vs[64*ATS];

    const int qt = (int)gridDim.x - 1 - (int)blockIdx.x;   // heavy tiles first
    const int bh = blockIdx.y;
    const int b  = bh / NH_;
    const int h  = bh - b * NH_;

    const int tid  = threadIdx.x;
    const int w    = tid >> 5;
    const int lane = tid & 31;
    const int gid  = lane >> 2;
    const int tig  = lane & 3;

    const size_t hoff = (size_t)h * HD_;
    const __half* Qg = Q + ((size_t)(b*S_ + qt*64)) * D_ + hoff;

    const __half2 sc2 = __floats2half2_rn(0.125f, 0.125f);
    for (int i = tid; i < 512; i += 128) {
        int r = i >> 3, c = (i & 7) * 8;
        uint4 u = *(const uint4*)(Qg + (size_t)r * D_ + c);
        __half2* hp = (__half2*)&u;
#pragma unroll
        for (int t = 0; t < 4; t++) hp[t] = __hmul2(hp[t], sc2);
        *(uint4*)&Qs[r*ATS + c] = u;
    }
    __syncthreads();

    const unsigned qb = (unsigned)__cvta_generic_to_shared(Qs);
    const unsigned kb = (unsigned)__cvta_generic_to_shared(Ks);
    const unsigned vb = (unsigned)__cvta_generic_to_shared(Vs);
    const int lrow = lane & 15;
    const int lcb  = (lane >> 4) * 8;

    unsigned aQ[4][4];
#pragma unroll
    for (int t = 0; t < 4; t++) {
        unsigned ad = qb + (unsigned)(((w*16 + lrow) * ATS + t*16 + lcb) * 2);
        asm volatile("ldmatrix.sync.aligned.m8n8.x4.shared.b16 {%0,%1,%2,%3}, [%4];"
                     : "=r"(aQ[t][0]), "=r"(aQ[t][1]), "=r"(aQ[t][2]), "=r"(aQ[t][3])
                     : "r"(ad));
    }

    float oacc[8][4];
#pragma unroll
    for (int j = 0; j < 8; j++)
#pragma unroll
        for (int c = 0; c < 4; c++) oacc[j][c] = 0.f;
    float m0 = -INFINITY, m1 = -INFINITY, l0 = 0.f, l1 = 0.f;

    const int r0l = w*16 + gid;
    const int r1l = r0l + 8;

    for (int kt = 0; kt <= qt; kt++) {
        __syncthreads();
        const __half* Kg = K + ((size_t)(b*S_ + kt*64)) * D_ + hoff;
        const __half* Vg = V + ((size_t)(b*S_ + kt*64)) * D_ + hoff;
        for (int i = tid; i < 1024; i += 128) {
            int r = (i >> 3) & 63, c = (i & 7) * 8;
            if (i < 512)
                *(uint4*)&Ks[r*ATS + c] = *(const uint4*)(Kg + (size_t)r * D_ + c);
            else
                *(uint4*)&Vs[r*ATS + c] = *(const uint4*)(Vg + (size_t)r * D_ + c);
        }
        __syncthreads();

        float sacc[8][4];
#pragma unroll
        for (int j = 0; j < 8; j++)
#pragma unroll
            for (int c = 0; c < 4; c++) sacc[j][c] = 0.f;

#pragma unroll
        for (int t = 0; t < 4; t++) {
#pragma unroll
            for (int jp = 0; jp < 4; jp++) {
                unsigned bk[4];
                unsigned ad = kb + (unsigned)(((jp*16 + lrow) * ATS + t*16 + lcb) * 2);
                asm volatile("ldmatrix.sync.aligned.m8n8.x4.shared.b16 {%0,%1,%2,%3}, [%4];"
                             : "=r"(bk[0]), "=r"(bk[1]), "=r"(bk[2]), "=r"(bk[3])
                             : "r"(ad));
                asm volatile(
                    "mma.sync.aligned.m16n8k16.row.col.f32.f16.f16.f32 "
                    "{%0,%1,%2,%3},{%4,%5,%6,%7},{%8,%9},{%0,%1,%2,%3};"
                    : "+f"(sacc[2*jp][0]), "+f"(sacc[2*jp][1]),
                      "+f"(sacc[2*jp][2]), "+f"(sacc[2*jp][3])
                    : "r"(aQ[t][0]), "r"(aQ[t][1]), "r"(aQ[t][2]), "r"(aQ[t][3]),
                      "r"(bk[0]), "r"(bk[2]));
                asm volatile(
                    "mma.sync.aligned.m16n8k16.row.col.f32.f16.f16.f32 "
                    "{%0,%1,%2,%3},{%4,%5,%6,%7},{%8,%9},{%0,%1,%2,%3};"
                    : "+f"(sacc[2*jp+1][0]), "+f"(sacc[2*jp+1][1]),
                      "+f"(sacc[2*jp+1][2]), "+f"(sacc[2*jp+1][3])
                    : "r"(aQ[t][0]), "r"(aQ[t][1]), "r"(aQ[t][2]), "r"(aQ[t][3]),
                      "r"(bk[1]), "r"(bk[3]));
            }
        }

        if (kt == qt) {
#pragma unroll
            for (int j = 0; j < 8; j++) {
                int c0 = j*8 + tig*2;
                if (c0     > r0l) sacc[j][0] = -INFINITY;
                if (c0 + 1 > r0l) sacc[j][1] = -INFINITY;
                if (c0     > r1l) sacc[j][2] = -INFINITY;
                if (c0 + 1 > r1l) sacc[j][3] = -INFINITY;
            }
        }

        float mx0 = -INFINITY, mx1 = -INFINITY;
#pragma unroll
        for (int j = 0; j < 8; j++) {
            mx0 = fmaxf(mx0, fmaxf(sacc[j][0], sacc[j][1]));
            mx1 = fmaxf(mx1, fmaxf(sacc[j][2], sacc[j][3]));
        }
#pragma unroll
        for (int o = 1; o <= 2; o <<= 1) {
            mx0 = fmaxf(mx0, __shfl_xor_sync(0xffffffffu, mx0, o));
            mx1 = fmaxf(mx1, __shfl_xor_sync(0xffffffffu, mx1, o));
        }
        float nm0 = fmaxf(m0, mx0), nm1 = fmaxf(m1, mx1);
        float corr0 = __expf(m0 - nm0), corr1 = __expf(m1 - nm1);

        unsigned pa0[8], pa1[8];
        float sum0 = 0.f, sum1 = 0.f;
#pragma unroll
        for (int j = 0; j < 8; j++) {
            float p00 = __expf(sacc[j][0] - nm0);
            float p01 = __expf(sacc[j][1] - nm0);
            float p10 = __expf(sacc[j][2] - nm1);
            float p11 = __expf(sacc[j][3] - nm1);
            sum0 += p00 + p01;
            sum1 += p10 + p11;
            __half2 h0 = __floats2half2_rn(p00, p01);
            __half2 h1 = __floats2half2_rn(p10, p11);
            pa0[j] = *(unsigned*)&h0;
            pa1[j] = *(unsigned*)&h1;
        }
#pragma unroll
        for (int o = 1; o <= 2; o <<= 1) {
            sum0 += __shfl_xor_sync(0xffffffffu, sum0, o);
            sum1 += __shfl_xor_sync(0xffffffffu, sum1, o);
        }
        l0 = l0 * corr0 + sum0;
        l1 = l1 * corr1 + sum1;
        m0 = nm0; m1 = nm1;
#pragma unroll
        for (int j = 0; j < 8; j++) {
            oacc[j][0] *= corr0; oacc[j][1] *= corr0;
            oacc[j][2] *= corr1; oacc[j][3] *= corr1;
        }

#pragma unroll
        for (int kc = 0; kc < 4; kc++) {
            unsigned a0 = pa0[2*kc], a1 = pa1[2*kc], a2 = pa0[2*kc+1], a3 = pa1[2*kc+1];
#pragma unroll
            for (int dp = 0; dp < 4; dp++) {
                unsigned bv[4];
                unsigned ad = vb + (unsigned)(((kc*16 + lrow) * ATS + dp*16 + lcb) * 2);
                asm volatile("ldmatrix.sync.aligned.m8n8.x4.trans.shared.b16 {%0,%1,%2,%3}, [%4];"
                             : "=r"(bv[0]), "=r"(bv[1]), "=r"(bv[2]), "=r"(bv[3])
                             : "r"(ad));
                asm volatile(
                    "mma.sync.aligned.m16n8k16.row.col.f32.f16.f16.f32 "
                    "{%0,%1,%2,%3},{%4,%5,%6,%7},{%8,%9},{%0,%1,%2,%3};"
                    : "+f"(oacc[2*dp][0]), "+f"(oacc[2*dp][1]),
                      "+f"(oacc[2*dp][2]), "+f"(oacc[2*dp][3])
                    : "r"(a0), "r"(a1), "r"(a2), "r"(a3),
                      "r"(bv[0]), "r"(bv[1]));
                asm volatile(
                    "mma.sync.aligned.m16n8k16.row.col.f32.f16.f16.f32 "
                    "{%0,%1,%2,%3},{%4,%5,%6,%7},{%8,%9},{%0,%1,%2,%3};"
                    : "+f"(oacc[2*dp+1][0]), "+f"(oacc[2*dp+1][1]),
                      "+f"(oacc[2*dp+1][2]), "+f"(oacc[2*dp+1][3])
                    : "r"(a0), "r"(a1), "r"(a2), "r"(a3),
                      "r"(bv[2]), "r"(bv[3]));
            }
        }
    }

    float inv0 = 1.f / l0, inv1 = 1.f / l1;
    size_t row0 = ((size_t)(b*S_ + qt*64 + r0l)) * D_ + hoff;
    size_t row1 = ((size_t)(b*S_ + qt*64 + r1l)) * D_ + hoff;
#pragma unroll
    for (int j = 0; j < 8; j++) {
        int c = j*8 + tig*2;
        __half2 o0 = __floats2half2_rn(oacc[j][0]*inv0, oacc[j][1]*inv0);
        __half2 o1 = __floats2half2_rn(oacc[j][2]*inv1, oacc[j][3]*inv1);
        *(__half2*)(O + row0 + c) = o0;
        *(__half2*)(O + row1 + c) = o1;
    }
}

// ---------------- LayerNorm over D (f32 in, f16 out) ------------------------
__global__ void ln_kernel(const float* __restrict__ H,
                          const float* __restrict__ g,
                          const float* __restrict__ bb,
                          __half* __restrict__ out)
{
    int row = blockIdx.x;
    const float* h = H + (size_t)row * D_;
    __shared__ float red[256];
    int tid = threadIdx.x;

    float s = 0.f;
    for (int i = tid; i < D_; i += 256) s += h[i];
    red[tid] = s; __syncthreads();
    for (int o = 128; o; o >>= 1) { if (tid < o) red[tid] += red[tid+o]; __syncthreads(); }
    float mu = red[0] / (float)D_;
    __syncthreads();

    float v = 0.f;
    for (int i = tid; i < D_; i += 256) { float d = h[i] - mu; v += d*d; }
    red[tid] = v; __syncthreads();
    for (int o = 128; o; o >>= 1) { if (tid < o) red[tid] += red[tid+o]; __syncthreads(); }
    float rstd = rsqrtf(red[0] / (float)D_ + 1e-5f);

    __half* o2 = out + (size_t)row * D_;
    for (int i = tid; i < D_; i += 256)
        o2[i] = __float2half((h[i] - mu) * rstd * g[i] + bb[i]);
}

// ---------------- loss from per-block partials -------------------------------
__global__ void loss_partials_kernel(const float* __restrict__ logits,
                                     const int* __restrict__ targets,
                                     const float* __restrict__ pmax,
                                     const float* __restrict__ psum,
                                     float* __restrict__ rowloss)
{
    int row = blockIdx.x;
    int tid = threadIdx.x;
    __shared__ float rm[128], rs[128];

    float m = NEG_, s = 0.f;
    for (int j = tid; j < NBLK_; j += 128) {
        float m2 = pmax[(size_t)row * NBLK_ + j];
        float s2 = psum[(size_t)row * NBLK_ + j];
        float mm = fmaxf(m, m2);
        s = s * __expf(m - mm) + s2 * __expf(m2 - mm);
        m = mm;
    }
    rm[tid] = m; rs[tid] = s; __syncthreads();
    for (int o = 64; o; o >>= 1) {
        if (tid < o) {
            float m1 = rm[tid], s1 = rs[tid];
            float m2 = rm[tid+o], s2 = rs[tid+o];
            float mm = fmaxf(m1, m2);
            rm[tid] = mm;
            rs[tid] = s1 * __expf(m1 - mm) + s2 * __expf(m2 - mm);
        }
        __syncthreads();
    }
    if (tid == 0)
        rowloss[row] = -(logits[(size_t)row * V_ + targets[row]] - rm[0] - logf(rs[0]));
}

__global__ void loss_reduce_kernel(const float* __restrict__ rowloss,
                                   float* __restrict__ out)
{
    __shared__ float red[256];
    int tid = threadIdx.x;
    float s = 0.f;
    for (int i = tid; i < T_; i += 256) s += rowloss[i];
    red[tid] = s; __syncthreads();
    for (int o = 128; o; o >>= 1) { if (tid < o) red[tid] += red[tid+o]; __syncthreads(); }
    if (tid == 0) out[0] = red[0] / (float)T_;
}

// ---------------- launcher ---------------------------------------------------
extern "C" void kernel_launch(void* const* d_in, const int* in_sizes, int n_in,
                              void* d_out, int out_size)
{
    const int*   inputs  = (const int*)  d_in[0];
    const int*   targets = (const int*)  d_in[1];
    const float* wte     = (const float*)d_in[2];
    const float* wq      = (const float*)d_in[3];
    const float* bq      = (const float*)d_in[4];
    const float* wk      = (const float*)d_in[5];
    const float* bk      = (const float*)d_in[6];
    const float* wv      = (const float*)d_in[7];
    const float* bv      = (const float*)d_in[8];
    const float* wo      = (const float*)d_in[9];
    const float* bo      = (const float*)d_in[10];
    const float* w1      = (const float*)d_in[11];
    const float* b1      = (const float*)d_in[12];
    const float* w2      = (const float*)d_in[13];
    const float* b2      = (const float*)d_in[14];
    const float* ln_g    = (const float*)d_in[15];
    const float* ln_b    = (const float*)d_in[16];
    const float* w_out   = (const float*)d_in[17];
    const float* b_out   = (const float*)d_in[18];
    float* out = (float*)d_out;

    __half *x,*q,*k,*v,*ctx,*ao,*h1,*hn,*w;
    float *h2,*rowloss,*pmax,*psum,*bqkv;
    cudaGetSymbolAddress((void**)&x,   g_x);
    cudaGetSymbolAddress((void**)&q,   g_q);
    cudaGetSymbolAddress((void**)&k,   g_k);
    cudaGetSymbolAddress((void**)&v,   g_v);
    cudaGetSymbolAddress((void**)&ctx, g_ctx);
    cudaGetSymbolAddress((void**)&ao,  g_ao);
    cudaGetSymbolAddress((void**)&h1,  g_h1);
    cudaGetSymbolAddress((void**)&h2,  g_h2);
    cudaGetSymbolAddress((void**)&hn,  g_hn);
    cudaGetSymbolAddress((void**)&rowloss, g_rowloss);
    cudaGetSymbolAddress((void**)&pmax, g_pmax);
    cudaGetSymbolAddress((void**)&psum, g_psum);
    cudaGetSymbolAddress((void**)&bqkv, g_bqkv);
    cudaGetSymbolAddress((void**)&w,   g_w);

    const int SMEM_GEMM = 3 * STGB;
    cudaFuncSetAttribute(hgemm_kernel, cudaFuncAttributeMaxDynamicSharedMemorySize, SMEM_GEMM);

    // 0. fused weight conversion (single launch)
    convert_all_kernel<<<(int)((CN5 + 255) / 256), 256>>>(
        wq, wk, wv, wo, w1, w2, w_out, bq, bk, bv, w, bqkv);

    // 1. embedding + positional encoding (fp16)
    embed_kernel<<<(T_*D_)/256, 256>>>(inputs, wte, x);

    // 2. fused Q,K,V projection (one GEMM, split epilogue)
    hgemm_kernel<<<dim3(T_/128, 3*D_/128), 256, SMEM_GEMM>>>(
        x, w+OFF_WQKV, bqkv, 0, q, k, v, 0, 0, 0, T_, 3*D_, D_, 3*D_, 0, 2);

    // 3. causal multi-head attention (heavy tiles first)
    attn_tc_kernel<<<dim3(S_/64, B_*NH_), 128>>>(q, k, v, ctx);

    // 4. output projection -> fp16 ao
    dim3 gDD(T_/128, D_/128);
    hgemm_kernel<<<gDD, 256, SMEM_GEMM>>>(
        ctx, w+OFF_WO, bo, ao, 0,0,0, 0,0,0, T_, D_, D_, D_, 0, 1);

    // 5. FFN (h1 fp16 + relu; h2 fp32 for LN)
    hgemm_kernel<<<dim3(T_/128, HID_/128), 256, SMEM_GEMM>>>(
        ao, w+OFF_W1, b1, h1, 0,0,0, 0,0,0, T_, HID_, D_, HID_, 1, 1);
    hgemm_kernel<<<gDD, 256, SMEM_GEMM>>>(
        h1, w+OFF_W2, b2, h2, 0,0,0, 0,0,0, T_, D_, HID_, D_, 0, 0);

    // 6. LayerNorm (fp32 in -> fp16 hn)
    ln_kernel<<<T_, 256>>>(h2, ln_g, ln_b, hn);

    // 7. vocab projection (BM=128, 2 CTAs/SM) -> fp32 logits + loss partials
    hgemm_kernel<<<dim3(T_/128, NBLK_), 256, SMEM_GEMM>>>(
        hn, w+OFF_WOUT, b_out, out, 0,0,0, pmax, psum, NBLK_,
        T_, V_, D_, VP2_, 0, 3);

    // 8. cross-entropy loss from partials
    loss_partials_kernel<<<T_, 128>>>(out, targets, pmax, psum, rowloss);
    if (out_size > T_ * V_)
        loss_reduce_kernel<<<1, 256>>>(rowloss, out + (size_t)T_ * V_);
}